// round 2
// baseline (speedup 1.0000x reference)
#include <cuda_runtime.h>
#include <cuda_bf16.h>

// ---------------- problem constants ----------------
#define NN     128      // batch
#define LL     512      // sequence length
#define HIDDEN 512
#define EMBED  256
#define DD     768      // HIDDEN + EMBED
#define GCTAS  128      // grid size (single wave on 148 SMs)
#define TTHR   256      // threads per CTA
#define KT     96       // k-tile (768 = 8 * 96)
#define NTILES 8
#define PADW   132      // floats per smem hx row (528B: 16B aligned, conflict-free)

// ---------------- persistent device state ----------------
__device__ float g_hT[2][HIDDEN * NN];          // h transposed [k][n], double buffered
__device__ float g_xT[LL][EMBED * NN];          // embedded inputs transposed [t][e][n] (64MB)
__device__ unsigned g_cnt;
__device__ volatile unsigned g_gen;

// ---------------- helpers ----------------
__device__ __forceinline__ void ffma2(unsigned long long& d, unsigned long long a,
                                      unsigned long long b) {
    asm volatile("fma.rn.f32x2 %0, %1, %2, %0;" : "+l"(d) : "l"(a), "l"(b));
}

__device__ __forceinline__ float2 unpack64(unsigned long long v) {
    float2 r;
    asm("mov.b64 {%0, %1}, %2;" : "=f"(r.x), "=f"(r.y) : "l"(v));
    return r;
}

__device__ __forceinline__ float sigmoidf_fast(float x) {
    return __fdividef(1.0f, 1.0f + __expf(-x));
}
__device__ __forceinline__ float tanhf_fast(float x) {
    return __fdividef(2.0f, 1.0f + __expf(-2.0f * x)) - 1.0f;
}

__device__ __forceinline__ void gridbarrier() {
    __syncthreads();
    if (threadIdx.x == 0) {
        unsigned my = g_gen;
        __threadfence();
        unsigned old = atomicAdd(&g_cnt, 1u);
        if (old == (GCTAS - 1)) {
            atomicExch(&g_cnt, 0u);
            __threadfence();
            g_gen = my + 1u;
        } else {
            while (g_gen == my) { __nanosleep(32); }
        }
        __threadfence();
    }
    __syncthreads();
}

// copy one 96x128 fp32 k-tile of hx^T into smem buffer cb via cp.async
#define COPY_TILE(kt_, cb_)                                                          \
    do {                                                                             \
        unsigned dbase = hx_u32 + (unsigned)((cb_) * (KT * PADW * 4));               \
        int kt0 = (kt_) * KT;                                                        \
        for (int u = tid; u < KT * 32; u += TTHR) {                                  \
            int row = u >> 5, seg = u & 31;                                          \
            int kg = kt0 + row;                                                      \
            const float* s = (kg < HIDDEN) ? (hsrc + kg * NN + seg * 4)              \
                                           : (xsrc + (kg - HIDDEN) * NN + seg * 4);  \
            unsigned d = dbase + (unsigned)(row * (PADW * 4) + seg * 16);            \
            asm volatile("cp.async.cg.shared.global [%0], [%1], 16;" ::"r"(d),       \
                         "l"(s));                                                    \
        }                                                                            \
        asm volatile("cp.async.commit_group;");                                      \
    } while (0)

// ---------------- persistent LSTM kernel ----------------
extern __shared__ char smem_raw[];

__global__ void __launch_bounds__(TTHR, 1)
lstm_persistent(const int* __restrict__ X, const float* __restrict__ E,
                const float* __restrict__ Wi, const float* __restrict__ bi,
                const float* __restrict__ Wf, const float* __restrict__ bf,
                const float* __restrict__ Wo, const float* __restrict__ bo,
                const float* __restrict__ Wh, const float* __restrict__ bh,
                float* __restrict__ out) {
    // smem layout: splatted weights [768][16] float2, then hx tiles [2][KT][PADW] float
    float2* W2 = (float2*)smem_raw;                         // 98304 B
    float* hxs = (float*)(smem_raw + DD * 16 * 8);          // 101376 B
    __shared__ int toks[NN];

    const int tid = threadIdx.x;
    const int rp  = tid >> 2;    // row pair 0..63 (rows 2rp, 2rp+1)
    const int cg  = tid & 3;     // which of this CTA's 4 h-columns
    const int hc0 = blockIdx.x * 4;
    const int hc  = hc0 + cg;

    // ---- load + splat this CTA's weight slice: W2[k][gate*4+cc] = (w, w) ----
    for (int i = tid; i < DD * 4; i += TTHR) {
        int k = i >> 2, cc = i & 3;
        float wi = Wi[k * HIDDEN + hc0 + cc];
        float wf = Wf[k * HIDDEN + hc0 + cc];
        float wo = Wo[k * HIDDEN + hc0 + cc];
        float wg = Wh[k * HIDDEN + hc0 + cc];
        W2[k * 16 + 0  + cc] = make_float2(wi, wi);
        W2[k * 16 + 4  + cc] = make_float2(wf, wf);
        W2[k * 16 + 8  + cc] = make_float2(wo, wo);
        W2[k * 16 + 12 + cc] = make_float2(wg, wg);
    }

    // ---- precompute transposed embeddings for this CTA's 4 timesteps ----
    for (int tt = 0; tt < 4; tt++) {
        int t = blockIdx.x * 4 + tt;
        __syncthreads();
        if (tid < NN) toks[tid] = X[tid * LL + t];
        __syncthreads();
        float* dst = g_xT[t];
        for (int i = tid; i < EMBED * NN; i += TTHR) {
            int e = i >> 7, n = i & 127;
            dst[i] = E[toks[n] * EMBED + e];
        }
    }

    // ---- zero initial h (buffer 0), c lives in registers ----
    for (int i = tid; i < 512; i += TTHR) g_hT[0][blockIdx.x * 512 + i] = 0.0f;

    const float b_i = bi[hc], b_f = bf[hc], b_o = bo[hc], b_g = bh[hc];
    float c0 = 0.0f, c1 = 0.0f;

    gridbarrier();

    const unsigned hx_u32 = (unsigned)__cvta_generic_to_shared(hxs);

    for (int t = 0; t < LL; t++) {
        const int p = t & 1;
        const float* hsrc = g_hT[p];
        const float* xsrc = g_xT[t];

        unsigned long long ai = 0ull, af = 0ull, ao = 0ull, ag = 0ull;

        COPY_TILE(0, 0);
        for (int kt = 0; kt < NTILES; kt++) {
            const int cb = kt & 1;
            if (kt + 1 < NTILES) {
                COPY_TILE(kt + 1, cb ^ 1);
                asm volatile("cp.async.wait_group 1;");
            } else {
                asm volatile("cp.async.wait_group 0;");
            }
            __syncthreads();

            const float* hb = hxs + cb * (KT * PADW) + 2 * rp;
            // NOTE: weights indexed by GLOBAL k -> include the kt*KT tile offset
            const float2* wb = W2 + cg + kt * (KT * 16);
#pragma unroll 8
            for (int k = 0; k < KT; k++) {
                unsigned long long a =
                    *(const unsigned long long*)(hb + k * PADW);
                const float2* w = wb + k * 16;
                ffma2(ai, a, *(const unsigned long long*)(w));
                ffma2(af, a, *(const unsigned long long*)(w + 4));
                ffma2(ao, a, *(const unsigned long long*)(w + 8));
                ffma2(ag, a, *(const unsigned long long*)(w + 12));
            }
            __syncthreads();
        }

        // ---- gate nonlinearities + state update (2 cells per thread) ----
        float2 vi = unpack64(ai), vf = unpack64(af), vo = unpack64(ao), vg = unpack64(ag);
        float i0 = sigmoidf_fast(vi.x + b_i), i1 = sigmoidf_fast(vi.y + b_i);
        float f0 = sigmoidf_fast(vf.x + b_f), f1 = sigmoidf_fast(vf.y + b_f);
        float o0 = sigmoidf_fast(vo.x + b_o), o1 = sigmoidf_fast(vo.y + b_o);
        float g0 = tanhf_fast(vg.x + b_g),    g1 = tanhf_fast(vg.y + b_g);

        c0 = f0 * c0 + i0 * g0;
        c1 = f1 * c1 + i1 * g1;
        float h0 = o0 * tanhf_fast(c0);
        float h1 = o1 * tanhf_fast(c1);

        *(float2*)(g_hT[p ^ 1] + hc * NN + 2 * rp) = make_float2(h0, h1);

        if (t == LL - 1) {
            out[(2 * rp) * HIDDEN + hc]     = h0;
            out[(2 * rp + 1) * HIDDEN + hc] = h1;
        }

        gridbarrier();
    }
}

// ---------------- launch ----------------
extern "C" void kernel_launch(void* const* d_in, const int* in_sizes, int n_in,
                              void* d_out, int out_size) {
    const int*   X  = (const int*)d_in[0];
    const float* E  = (const float*)d_in[1];
    const float* Wi = (const float*)d_in[2];
    const float* bi = (const float*)d_in[3];
    const float* Wf = (const float*)d_in[4];
    const float* bf = (const float*)d_in[5];
    const float* Wo = (const float*)d_in[6];
    const float* bo = (const float*)d_in[7];
    const float* Wh = (const float*)d_in[8];
    const float* bh = (const float*)d_in[9];
    float* out = (float*)d_out;

    const int smem_bytes = DD * 16 * 8 + 2 * KT * PADW * 4;  // 98304 + 101376 = 199680
    cudaFuncSetAttribute(lstm_persistent,
                         cudaFuncAttributeMaxDynamicSharedMemorySize, smem_bytes);

    lstm_persistent<<<GCTAS, TTHR, smem_bytes>>>(X, E, Wi, bi, Wf, bf, Wo, bo, Wh, bh,
                                                 out);
}

// round 3
// speedup vs baseline: 2.3056x; 2.3056x over previous
#include <cuda_runtime.h>
#include <cuda_bf16.h>

// ---------------- problem constants ----------------
#define NN     128      // batch
#define LL     512      // sequence length
#define HIDDEN 512
#define EMBED  256
#define DD     768      // HIDDEN + EMBED
#define GCTAS  128
#define TTHR   256      // 8 warps
#define KT     96       // k-tile rows (768 = 8 * 96)
#define NTILES 8
#define PADA   68       // floats per staged activation row (272B, 16B aligned)

// thread blocking: Nb=16 batch, Cb=2 cols, k split 16 ways (8 warps x 2 half-warps)
// CTA covers 8 columns x 64 batch. 512 cols/8 * 2 n-halves = 128 CTAs.

// smem layout (dynamic):
#define SM_W    0                       // 768*32 floats  = 98304 B (w[k][c][g] scalar)
#define SM_HX   98304                   // 2*96*68 floats = 52224 B
#define SM_RED  150528                  // 8*64*17 ull    = 69632 B (padded)
#define SM_TOT  220160

// ---------------- persistent device state ----------------
__device__ float g_hT[2][HIDDEN * NN];      // h transposed [col][n]
__device__ float g_xT[LL][EMBED * NN];      // embedded inputs transposed [t][e][n]
__device__ unsigned g_cnt;
__device__ volatile unsigned g_gen;

// ---------------- helpers ----------------
__device__ __forceinline__ void ffma2(unsigned long long& d, unsigned long long a,
                                      unsigned long long b) {
    asm volatile("fma.rn.f32x2 %0, %1, %2, %0;" : "+l"(d) : "l"(a), "l"(b));
}
__device__ __forceinline__ unsigned long long add2(unsigned long long a,
                                                   unsigned long long b) {
    unsigned long long r;
    asm("add.rn.f32x2 %0, %1, %2;" : "=l"(r) : "l"(a), "l"(b));
    return r;
}
__device__ __forceinline__ unsigned long long pack2(float v) {
    unsigned long long r;
    asm("mov.b64 %0, {%1, %1};" : "=l"(r) : "f"(v));
    return r;
}
__device__ __forceinline__ float2 unpack64(unsigned long long v) {
    float2 r;
    asm("mov.b64 {%0, %1}, %2;" : "=f"(r.x), "=f"(r.y) : "l"(v));
    return r;
}
__device__ __forceinline__ float sigmoidf_fast(float x) {
    return __fdividef(1.0f, 1.0f + __expf(-x));
}
__device__ __forceinline__ float tanhf_fast(float x) {
    return __fdividef(2.0f, 1.0f + __expf(-2.0f * x)) - 1.0f;
}

__device__ __forceinline__ void gridbarrier() {
    __syncthreads();
    if (threadIdx.x == 0) {
        unsigned my = g_gen;
        __threadfence();
        unsigned old = atomicAdd(&g_cnt, 1u);
        if (old == (GCTAS - 1)) {
            atomicExch(&g_cnt, 0u);
            __threadfence();
            g_gen = my + 1u;
        } else {
            while (g_gen == my) { __nanosleep(32); }
        }
        __threadfence();
    }
    __syncthreads();
}

// stage one 96k x 64n fp32 tile of hx^T (this CTA's n-half) into smem buffer cb_
#define COPY_TILE(kt_, cb_)                                                           \
    do {                                                                              \
        unsigned dbase = hx_u32 + (unsigned)((cb_) * (KT * PADA * 4));                \
        int kt0 = (kt_) * KT;                                                         \
        _Pragma("unroll")                                                             \
        for (int u = tid; u < KT * 16; u += TTHR) {                                   \
            int row = u >> 4, ch = u & 15;                                            \
            int kg = kt0 + row;                                                       \
            const float* s = ((kg < HIDDEN) ? (hsrc + kg * NN)                        \
                                            : (xsrc + (kg - HIDDEN) * NN)) +          \
                             nbase + ch * 4;                                          \
            unsigned d = dbase + (unsigned)(row * (PADA * 4) + ch * 16);              \
            asm volatile("cp.async.cg.shared.global [%0], [%1], 16;" ::"r"(d),        \
                         "l"(s));                                                     \
        }                                                                             \
        asm volatile("cp.async.commit_group;");                                      \
    } while (0)

extern __shared__ char smem_raw[];

__global__ void __launch_bounds__(TTHR, 1)
lstm_persistent(const int* __restrict__ X, const float* __restrict__ E,
                const float* __restrict__ Wi, const float* __restrict__ bi,
                const float* __restrict__ Wf, const float* __restrict__ bf,
                const float* __restrict__ Wo, const float* __restrict__ bo,
                const float* __restrict__ Wh, const float* __restrict__ bh,
                float* __restrict__ out) {
    float* Wsm = (float*)(smem_raw + SM_W);
    float* hxs = (float*)(smem_raw + SM_HX);
    unsigned long long* red = (unsigned long long*)(smem_raw + SM_RED);
    __shared__ int toks[NN];

    const int tid   = threadIdx.x;
    const int warp  = tid >> 5;
    const int lane  = tid & 31;
    const int kp_lo = lane >> 4;         // k sub-phase within warp
    const int ng    = (lane >> 2) & 3;   // n-group (16 n each)
    const int cg    = lane & 3;          // col-pair group (2 cols each)

    const int colgrp = blockIdx.x >> 1;
    const int nh     = blockIdx.x & 1;
    const int colbase = colgrp * 8;
    const int nbase   = nh * 64;

    // ---- load this CTA's weight slice into smem: Wsm[k*32 + c*4 + g] (scalar) ----
    for (int i = tid; i < DD * 8; i += TTHR) {
        int k = i >> 3, c = i & 7;
        int col = colbase + c;
        float* w = Wsm + k * 32 + c * 4;
        w[0] = Wi[k * HIDDEN + col];
        w[1] = Wf[k * HIDDEN + col];
        w[2] = Wo[k * HIDDEN + col];
        w[3] = Wh[k * HIDDEN + col];
    }

    // ---- precompute transposed embeddings (each CTA handles 4 timesteps, all n) ----
    for (int tt = 0; tt < 4; tt++) {
        int t = blockIdx.x * 4 + tt;
        __syncthreads();
        if (tid < NN) toks[tid] = X[tid * LL + t];
        __syncthreads();
        float* dst = g_xT[t];
        for (int i = tid; i < EMBED * NN; i += TTHR) {
            int e = i >> 7, n = i & 127;
            dst[i] = E[toks[n] * EMBED + e];
        }
    }

    // ---- zero initial h (buffer 0) ----
    for (int i = tid; i < 512; i += TTHR) g_hT[0][blockIdx.x * 512 + i] = 0.0f;

    // ---- epilogue role: this thread owns cell (col_e, n-pair np_e) ----
    const int ce   = tid & 7;       // col within group
    const int np_e = tid >> 3;      // n-pair 0..31
    const int col_e = colbase + ce;
    const int cge = ce >> 1, cce = ce & 1;
    const int nge = np_e >> 3, je = np_e & 7;
    const int slot_e = nge * 4 + cge;
    const float b_i = bi[col_e], b_f = bf[col_e], b_o = bo[col_e], b_g = bh[col_e];
    float cs0 = 0.0f, cs1 = 0.0f;

    gridbarrier();

    const unsigned hx_u32 = (unsigned)__cvta_generic_to_shared(hxs);
    const int klane = warp * 2 + kp_lo;   // this thread's k residue mod 16
    const int slot_w = ng * 4 + cg;       // reduction write slot

    for (int t = 0; t < LL; t++) {
        const int p = t & 1;
        const float* hsrc = g_hT[p];
        const float* xsrc = g_xT[t];

        // 64 packed-f32x2 accumulators: index r = g*16 + j*2 + cc
        unsigned long long acc[64];
#pragma unroll
        for (int r = 0; r < 64; r++) acc[r] = 0ull;

        COPY_TILE(0, 0);
        for (int kt = 0; kt < NTILES; kt++) {
            const int cb = kt & 1;
            if (kt + 1 < NTILES) {
                COPY_TILE(kt + 1, cb ^ 1);
                asm volatile("cp.async.wait_group 1;");
            } else {
                asm volatile("cp.async.wait_group 0;");
            }
            __syncthreads();

            const float* hxb = hxs + cb * (KT * PADA);
#pragma unroll
            for (int jj = 0; jj < 6; jj++) {
                const int kl = klane + 16 * jj;
                const int kg = kt * KT + kl;
                // activations: 16 n = 8 packed pairs
                const ulonglong2* ap =
                    (const ulonglong2*)(hxb + kl * PADA + ng * 16);
                ulonglong2 a0 = ap[0], a1 = ap[1], a2 = ap[2], a3 = ap[3];
                unsigned long long av[8] = {a0.x, a0.y, a1.x, a1.y,
                                            a2.x, a2.y, a3.x, a3.y};
                // weights: 2 cols x 4 gates (scalar), pack to (w,w)
                const float4* wp = (const float4*)(Wsm + kg * 32 + cg * 8);
                float4 w0 = wp[0], w1 = wp[1];
                unsigned long long wpk[2][4];
                wpk[0][0] = pack2(w0.x); wpk[0][1] = pack2(w0.y);
                wpk[0][2] = pack2(w0.z); wpk[0][3] = pack2(w0.w);
                wpk[1][0] = pack2(w1.x); wpk[1][1] = pack2(w1.y);
                wpk[1][2] = pack2(w1.z); wpk[1][3] = pack2(w1.w);
#pragma unroll
                for (int g = 0; g < 4; g++)
#pragma unroll
                    for (int j = 0; j < 8; j++) {
                        ffma2(acc[g * 16 + j * 2 + 0], av[j], wpk[0][g]);
                        ffma2(acc[g * 16 + j * 2 + 1], av[j], wpk[1][g]);
                    }
            }
            __syncthreads();
        }

        // ---- reduce the 2 k-phases within each warp ----
#pragma unroll
        for (int r = 0; r < 64; r++) {
            unsigned long long o = __shfl_xor_sync(0xffffffffu, acc[r], 16);
            acc[r] = add2(acc[r], o);
        }
        // ---- write warp partials to smem: red[(warp*64 + r)*17 + slot] ----
        if (kp_lo == 0) {
#pragma unroll
            for (int r = 0; r < 64; r++)
                red[(warp * 64 + r) * 17 + slot_w] = acc[r];
        }
        __syncthreads();

        // ---- gather 8 warp partials + gates + state update ----
        unsigned long long s[4];
#pragma unroll
        for (int g = 0; g < 4; g++) {
            int r = g * 16 + je * 2 + cce;
            unsigned long long v = red[r * 17 + slot_e];
#pragma unroll
            for (int pp = 1; pp < 8; pp++)
                v = add2(v, red[(pp * 64 + r) * 17 + slot_e]);
            s[g] = v;
        }
        float2 vi = unpack64(s[0]), vf = unpack64(s[1]);
        float2 vo = unpack64(s[2]), vg = unpack64(s[3]);
        float i0 = sigmoidf_fast(vi.x + b_i), i1 = sigmoidf_fast(vi.y + b_i);
        float f0 = sigmoidf_fast(vf.x + b_f), f1 = sigmoidf_fast(vf.y + b_f);
        float o0 = sigmoidf_fast(vo.x + b_o), o1 = sigmoidf_fast(vo.y + b_o);
        float g0 = tanhf_fast(vg.x + b_g),    g1 = tanhf_fast(vg.y + b_g);

        cs0 = f0 * cs0 + i0 * g0;
        cs1 = f1 * cs1 + i1 * g1;
        float h0 = o0 * tanhf_fast(cs0);
        float h1 = o1 * tanhf_fast(cs1);

        *(float2*)(g_hT[p ^ 1] + col_e * NN + nbase + 2 * np_e) =
            make_float2(h0, h1);

        if (t == LL - 1) {
            out[(nbase + 2 * np_e) * HIDDEN + col_e]     = h0;
            out[(nbase + 2 * np_e + 1) * HIDDEN + col_e] = h1;
        }

        gridbarrier();
    }
}

// ---------------- launch ----------------
extern "C" void kernel_launch(void* const* d_in, const int* in_sizes, int n_in,
                              void* d_out, int out_size) {
    const int*   X  = (const int*)d_in[0];
    const float* E  = (const float*)d_in[1];
    const float* Wi = (const float*)d_in[2];
    const float* bi = (const float*)d_in[3];
    const float* Wf = (const float*)d_in[4];
    const float* bf = (const float*)d_in[5];
    const float* Wo = (const float*)d_in[6];
    const float* bo = (const float*)d_in[7];
    const float* Wh = (const float*)d_in[8];
    const float* bh = (const float*)d_in[9];
    float* out = (float*)d_out;

    cudaFuncSetAttribute(lstm_persistent,
                         cudaFuncAttributeMaxDynamicSharedMemorySize, SM_TOT);

    lstm_persistent<<<GCTAS, TTHR, SM_TOT>>>(X, E, Wi, bi, Wf, bf, Wo, bo, Wh, bh,
                                             out);
}

// round 4
// speedup vs baseline: 2.6054x; 1.1300x over previous
#include <cuda_runtime.h>
#include <cuda_bf16.h>

// ---------------- problem constants ----------------
#define NN     128      // batch
#define LL     512      // sequence length
#define HIDDEN 512
#define EMBED  256
#define DD     768      // HIDDEN + EMBED
#define GCTAS  128
#define TTHR   256      // 8 warps
#define KT     96       // k-tile rows (768 = 8 * 96)
#define NTILES 8
#define PADA   68       // floats per staged activation row

// Logical k permutation: j in [0,256) -> x row j ; j in [256,768) -> h row j-256.
// Tiles 0,1 are pure x (no cross-CTA dependency); h first needed in tile 2.

// smem layout (dynamic):
#define SM_W    0                       // 768*32 floats  = 98304 B
#define SM_HX   98304                   // 2*96*68 floats = 52224 B
#define SM_RED  150528                  // 8*64*17 ull    = 69632 B
#define SM_TOT  220160

// ---------------- persistent device state ----------------
__device__ float g_hT[2][HIDDEN * NN];      // h transposed [col][n], buffer t&1 holds h_{t-1}
__device__ float g_xT[LL][EMBED * NN];      // embedded inputs transposed [t][e][n]
// entry barrier (sense-reversing, replay-safe)
__device__ unsigned g_ecnt;
__device__ volatile unsigned g_egen;
// main-loop h-publication tracking (reset each launch before entry barrier)
__device__ unsigned g_cnt1[16 * 32];        // level-1 counters, 128B apart
__device__ unsigned g_cnt2;                 // level-2 counter
__device__ volatile unsigned g_gen;         // == t+1 when h_t fully published

// ---------------- helpers ----------------
__device__ __forceinline__ void ffma2(unsigned long long& d, unsigned long long a,
                                      unsigned long long b) {
    asm volatile("fma.rn.f32x2 %0, %1, %2, %0;" : "+l"(d) : "l"(a), "l"(b));
}
__device__ __forceinline__ unsigned long long add2(unsigned long long a,
                                                   unsigned long long b) {
    unsigned long long r;
    asm("add.rn.f32x2 %0, %1, %2;" : "=l"(r) : "l"(a), "l"(b));
    return r;
}
__device__ __forceinline__ unsigned long long pack2(float v) {
    unsigned long long r;
    asm("mov.b64 %0, {%1, %1};" : "=l"(r) : "f"(v));
    return r;
}
__device__ __forceinline__ float2 unpack64(unsigned long long v) {
    float2 r;
    asm("mov.b64 {%0, %1}, %2;" : "=f"(r.x), "=f"(r.y) : "l"(v));
    return r;
}
__device__ __forceinline__ float sigmoidf_fast(float x) {
    return __fdividef(1.0f, 1.0f + __expf(-x));
}
__device__ __forceinline__ float tanhf_fast(float x) {
    return __fdividef(2.0f, 1.0f + __expf(-2.0f * x)) - 1.0f;
}

// full entry barrier (used once per launch)
__device__ __forceinline__ void entrybarrier() {
    __syncthreads();
    if (threadIdx.x == 0) {
        unsigned my = g_egen;
        __threadfence();
        unsigned old = atomicAdd(&g_ecnt, 1u);
        if (old == (GCTAS - 1)) {
            atomicExch(&g_ecnt, 0u);
            __threadfence();
            g_egen = my + 1u;
        } else {
            while (g_egen == my) { __nanosleep(64); }
        }
        __threadfence();
    }
    __syncthreads();
}

// stage one 96-row x 64-n tile (logical k space) into smem buffer cb_
#define COPY_TILE(xs_, hs_, kt_, cb_)                                                 \
    do {                                                                              \
        unsigned dbase = hx_u32 + (unsigned)((cb_) * (KT * PADA * 4));                \
        int kt0 = (kt_) * KT;                                                         \
        _Pragma("unroll")                                                             \
        for (int u = tid; u < KT * 16; u += TTHR) {                                   \
            int row = u >> 4, ch = u & 15;                                            \
            int j = kt0 + row;                                                        \
            const float* s = ((j < 256) ? ((xs_) + j * NN)                            \
                                        : ((hs_) + (j - 256) * NN)) +                 \
                             nbase + ch * 4;                                          \
            unsigned d = dbase + (unsigned)(row * (PADA * 4) + ch * 16);              \
            asm volatile("cp.async.cg.shared.global [%0], [%1], 16;" ::"r"(d),        \
                         "l"(s));                                                     \
        }                                                                             \
        asm volatile("cp.async.commit_group;");                                      \
    } while (0)

// compute one staged tile into the 64 packed accumulators
#define COMPUTE_TILE(kt_, cb_)                                                        \
    do {                                                                              \
        const float* hxb = hxs + (cb_) * (KT * PADA);                                 \
        _Pragma("unroll")                                                             \
        for (int jj = 0; jj < 6; jj++) {                                              \
            const int kl = klane + 16 * jj;                                           \
            const int jg = (kt_) * KT + kl;                                           \
            const ulonglong2* ap = (const ulonglong2*)(hxb + kl * PADA + ng * 16);    \
            ulonglong2 a0 = ap[0], a1 = ap[1], a2 = ap[2], a3 = ap[3];                \
            unsigned long long av[8] = {a0.x, a0.y, a1.x, a1.y,                       \
                                        a2.x, a2.y, a3.x, a3.y};                      \
            const float4* wp = (const float4*)(Wsm + jg * 32 + cg * 8);               \
            float4 w0 = wp[0], w1 = wp[1];                                            \
            unsigned long long wpk[2][4];                                             \
            wpk[0][0] = pack2(w0.x); wpk[0][1] = pack2(w0.y);                         \
            wpk[0][2] = pack2(w0.z); wpk[0][3] = pack2(w0.w);                         \
            wpk[1][0] = pack2(w1.x); wpk[1][1] = pack2(w1.y);                         \
            wpk[1][2] = pack2(w1.z); wpk[1][3] = pack2(w1.w);                         \
            _Pragma("unroll")                                                         \
            for (int g = 0; g < 4; g++)                                               \
                _Pragma("unroll")                                                     \
                for (int j = 0; j < 8; j++) {                                         \
                    ffma2(acc[g * 16 + j * 2 + 0], av[j], wpk[0][g]);                 \
                    ffma2(acc[g * 16 + j * 2 + 1], av[j], wpk[1][g]);                 \
                }                                                                     \
        }                                                                             \
    } while (0)

#define WAITG1 asm volatile("cp.async.wait_group 1;")

extern __shared__ char smem_raw[];

__global__ void __launch_bounds__(TTHR, 1)
lstm_persistent(const int* __restrict__ X, const float* __restrict__ E,
                const float* __restrict__ Wi, const float* __restrict__ bi,
                const float* __restrict__ Wf, const float* __restrict__ bf,
                const float* __restrict__ Wo, const float* __restrict__ bo,
                const float* __restrict__ Wh, const float* __restrict__ bh,
                float* __restrict__ out) {
    float* Wsm = (float*)(smem_raw + SM_W);
    float* hxs = (float*)(smem_raw + SM_HX);
    unsigned long long* red = (unsigned long long*)(smem_raw + SM_RED);
    __shared__ int toks[NN];

    const int tid   = threadIdx.x;
    const int warp  = tid >> 5;
    const int lane  = tid & 31;
    const int kp_lo = lane >> 4;
    const int ng    = (lane >> 2) & 3;
    const int cg    = lane & 3;

    const int colgrp = blockIdx.x >> 1;
    const int nh     = blockIdx.x & 1;
    const int colbase = colgrp * 8;
    const int nbase   = nh * 64;
    const int grp     = blockIdx.x >> 3;   // arrival group (16 groups of 8)

    // ---- reset per-launch counters (replay safety) ----
    if (blockIdx.x == 0 && tid < 32) {
        if (tid < 16) g_cnt1[tid * 32] = 0u;
        if (tid == 16) g_cnt2 = 0u;
        if (tid == 17) g_gen = 0u;
    }

    // ---- load weights into smem, PERMUTED k order: j<256 -> x(512+j), else h(j-256) ----
    for (int i = tid; i < DD * 8; i += TTHR) {
        int j = i >> 3, c = i & 7;
        int k = (j < 256) ? (512 + j) : (j - 256);
        int col = colbase + c;
        float* w = Wsm + j * 32 + c * 4;
        w[0] = Wi[k * HIDDEN + col];
        w[1] = Wf[k * HIDDEN + col];
        w[2] = Wo[k * HIDDEN + col];
        w[3] = Wh[k * HIDDEN + col];
    }

    // ---- precompute transposed embeddings (each CTA handles 4 timesteps) ----
    for (int tt = 0; tt < 4; tt++) {
        int t = blockIdx.x * 4 + tt;
        __syncthreads();
        if (tid < NN) toks[tid] = X[tid * LL + t];
        __syncthreads();
        float* dst = g_xT[t];
        for (int i = tid; i < EMBED * NN; i += TTHR) {
            int e = i >> 7, n = i & 127;
            dst[i] = E[toks[n] * EMBED + e];
        }
    }

    // ---- zero initial h (buffer 0) ----
    for (int i = tid; i < 512; i += TTHR) g_hT[0][blockIdx.x * 512 + i] = 0.0f;

    // ---- epilogue role ----
    const int ce    = tid & 7;
    const int np_e  = tid >> 3;
    const int col_e = colbase + ce;
    const int cge = ce >> 1, cce = ce & 1;
    const int nge = np_e >> 3, je = np_e & 7;
    const int slot_e = nge * 4 + cge;
    const float b_i = bi[col_e], b_f = bf[col_e], b_o = bo[col_e], b_g = bh[col_e];
    float cs0 = 0.0f, cs1 = 0.0f;

    entrybarrier();   // embeds + h0 + counter resets globally visible

    const unsigned hx_u32 = (unsigned)__cvta_generic_to_shared(hxs);
    const int klane  = warp * 2 + kp_lo;
    const int slot_w = ng * 4 + cg;

    // prologue: x tiles 0,1 of step 0
    COPY_TILE(g_xT[0], g_hT[0], 0, 0);
    COPY_TILE(g_xT[0], g_hT[0], 1, 1);

    for (int t = 0; t < LL; t++) {
        const int p = t & 1;
        const float* hsrc = g_hT[p];
        const float* xsrc = g_xT[t];

        unsigned long long acc[64];
#pragma unroll
        for (int r = 0; r < 64; r++) acc[r] = 0ull;

        // tile 0 (pure x)
        WAITG1; __syncthreads();
        COMPUTE_TILE(0, 0);
        __syncthreads();
        // h_{t-1} must be published before we read it (tile 2 onward)
        if ((int)g_gen < t) {
            while ((int)g_gen < t) { __nanosleep(64); }
        }
        COPY_TILE(xsrc, hsrc, 2, 0);

        // tile 1 (pure x)
        WAITG1; __syncthreads();
        COMPUTE_TILE(1, 1);
        __syncthreads();
        COPY_TILE(xsrc, hsrc, 3, 1);

        // tiles 2..5
        WAITG1; __syncthreads();
        COMPUTE_TILE(2, 0);
        __syncthreads();
        COPY_TILE(xsrc, hsrc, 4, 0);

        WAITG1; __syncthreads();
        COMPUTE_TILE(3, 1);
        __syncthreads();
        COPY_TILE(xsrc, hsrc, 5, 1);

        WAITG1; __syncthreads();
        COMPUTE_TILE(4, 0);
        __syncthreads();
        COPY_TILE(xsrc, hsrc, 6, 0);

        WAITG1; __syncthreads();
        COMPUTE_TILE(5, 1);
        __syncthreads();
        COPY_TILE(xsrc, hsrc, 7, 1);

        // tile 6; afterwards prefetch next step's x tile 0
        WAITG1; __syncthreads();
        COMPUTE_TILE(6, 0);
        __syncthreads();
        if (t + 1 < LL) COPY_TILE(g_xT[t + 1], hsrc, 0, 0);

        // tile 7; afterwards prefetch next step's x tile 1
        WAITG1; __syncthreads();
        COMPUTE_TILE(7, 1);
        __syncthreads();
        if (t + 1 < LL) COPY_TILE(g_xT[t + 1], hsrc, 1, 1);

        // ---- reduce 2 k-phases within warp ----
#pragma unroll
        for (int r = 0; r < 64; r++) {
            unsigned long long o = __shfl_xor_sync(0xffffffffu, acc[r], 16);
            acc[r] = add2(acc[r], o);
        }
        if (kp_lo == 0) {
#pragma unroll
            for (int r = 0; r < 64; r++)
                red[(warp * 64 + r) * 17 + slot_w] = acc[r];
        }
        __syncthreads();

        // ---- gather 8 warp partials + gates + state update ----
        unsigned long long s[4];
#pragma unroll
        for (int g = 0; g < 4; g++) {
            int r = g * 16 + je * 2 + cce;
            unsigned long long v = red[r * 17 + slot_e];
#pragma unroll
            for (int pp = 1; pp < 8; pp++)
                v = add2(v, red[(pp * 64 + r) * 17 + slot_e]);
            s[g] = v;
        }
        float2 vi = unpack64(s[0]), vf = unpack64(s[1]);
        float2 vo = unpack64(s[2]), vg = unpack64(s[3]);
        float i0 = sigmoidf_fast(vi.x + b_i), i1 = sigmoidf_fast(vi.y + b_i);
        float f0 = sigmoidf_fast(vf.x + b_f), f1 = sigmoidf_fast(vf.y + b_f);
        float o0 = sigmoidf_fast(vo.x + b_o), o1 = sigmoidf_fast(vo.y + b_o);
        float g0 = tanhf_fast(vg.x + b_g),    g1 = tanhf_fast(vg.y + b_g);

        cs0 = f0 * cs0 + i0 * g0;
        cs1 = f1 * cs1 + i1 * g1;
        float h0 = o0 * tanhf_fast(cs0);
        float h1 = o1 * tanhf_fast(cs1);

        *(float2*)(g_hT[p ^ 1] + col_e * NN + nbase + 2 * np_e) =
            make_float2(h0, h1);

        if (t == LL - 1) {
            out[(nbase + 2 * np_e) * HIDDEN + col_e]     = h0;
            out[(nbase + 2 * np_e + 1) * HIDDEN + col_e] = h1;
        }

        // ---- publish h_t: per-thread fence, then two-level arrival (no wait!) ----
        __threadfence();
        __syncthreads();
        if (tid == 0) {
            unsigned o1 = atomicAdd(&g_cnt1[grp * 32], 1u);
            if ((o1 & 7u) == 7u) {
                unsigned o2 = atomicAdd(&g_cnt2, 1u);
                if ((o2 & 15u) == 15u) {
                    __threadfence();
                    g_gen = (unsigned)(t + 1);
                }
            }
        }
    }
}

// ---------------- launch ----------------
extern "C" void kernel_launch(void* const* d_in, const int* in_sizes, int n_in,
                              void* d_out, int out_size) {
    const int*   X  = (const int*)d_in[0];
    const float* E  = (const float*)d_in[1];
    const float* Wi = (const float*)d_in[2];
    const float* bi = (const float*)d_in[3];
    const float* Wf = (const float*)d_in[4];
    const float* bf = (const float*)d_in[5];
    const float* Wo = (const float*)d_in[6];
    const float* bo = (const float*)d_in[7];
    const float* Wh = (const float*)d_in[8];
    const float* bh = (const float*)d_in[9];
    float* out = (float*)d_out;

    cudaFuncSetAttribute(lstm_persistent,
                         cudaFuncAttributeMaxDynamicSharedMemorySize, SM_TOT);

    lstm_persistent<<<GCTAS, TTHR, SM_TOT>>>(X, E, Wi, bi, Wf, bf, Wo, bo, Wh, bh,
                                             out);
}

// round 5
// speedup vs baseline: 2.7418x; 1.0523x over previous
#include <cuda_runtime.h>
#include <cuda_bf16.h>

// ---------------- problem constants ----------------
#define NN     128      // batch
#define LL     512      // sequence length
#define HIDDEN 512
#define EMBED  256
#define DD     768      // HIDDEN + EMBED
#define GCTAS  128
#define TTHR   256      // 8 warps
#define KT     96       // k-tile rows (768 = 8 * 96)
#define NTILES 8
#define PADA   68       // floats per staged activation row

// Logical k permutation: j in [0,256) -> x row j ; j in [256,768) -> h row j-256.
// Tiles 0,1 are pure x (no cross-CTA dependency); h first needed in tile 2.

// smem layout (dynamic):
#define SM_W    0                       // 768*32 floats  = 98304 B
#define SM_HX   98304                   // 2*96*68 floats = 52224 B
#define SM_RED  150528                  // 8*64*17 ull    = 69632 B
#define SM_TOT  220160

// ---------------- persistent device state ----------------
__device__ float g_hT[2][HIDDEN * NN];      // h transposed [col][n], buffer t&1 holds h_{t-1}
__device__ float g_xT[LL][EMBED * NN];      // embedded inputs transposed [t][e][n]
// entry barrier (sense-reversing, replay-safe)
__device__ unsigned g_ecnt;
__device__ volatile unsigned g_egen;
// main-loop h-publication tracking (reset each launch before entry barrier)
__device__ unsigned g_cnt1[16 * 32];        // level-1 counters, 128B apart
__device__ unsigned g_cnt2;                 // level-2 counter
__device__ volatile unsigned g_gen;         // == t+1 when h_t fully published

// ---------------- helpers ----------------
__device__ __forceinline__ void ffma2(unsigned long long& d, unsigned long long a,
                                      unsigned long long b) {
    asm volatile("fma.rn.f32x2 %0, %1, %2, %0;" : "+l"(d) : "l"(a), "l"(b));
}
__device__ __forceinline__ unsigned long long add2(unsigned long long a,
                                                   unsigned long long b) {
    unsigned long long r;
    asm("add.rn.f32x2 %0, %1, %2;" : "=l"(r) : "l"(a), "l"(b));
    return r;
}
__device__ __forceinline__ unsigned long long pack2(float v) {
    unsigned long long r;
    asm("mov.b64 %0, {%1, %1};" : "=l"(r) : "f"(v));
    return r;
}
__device__ __forceinline__ float2 unpack64(unsigned long long v) {
    float2 r;
    asm("mov.b64 {%0, %1}, %2;" : "=f"(r.x), "=f"(r.y) : "l"(v));
    return r;
}
__device__ __forceinline__ float sigmoidf_fast(float x) {
    return __fdividef(1.0f, 1.0f + __expf(-x));
}
__device__ __forceinline__ float tanhf_fast(float x) {
    return __fdividef(2.0f, 1.0f + __expf(-2.0f * x)) - 1.0f;
}

// full entry barrier (used once per launch)
__device__ __forceinline__ void entrybarrier() {
    __syncthreads();
    if (threadIdx.x == 0) {
        unsigned my = g_egen;
        __threadfence();
        unsigned old = atomicAdd(&g_ecnt, 1u);
        if (old == (GCTAS - 1)) {
            atomicExch(&g_ecnt, 0u);
            __threadfence();
            g_egen = my + 1u;
        } else {
            while (g_egen == my) { __nanosleep(64); }
        }
        __threadfence();
    }
    __syncthreads();
}

// stage one 96-row x 64-n tile (logical k space) into smem buffer cb_
#define COPY_TILE(xs_, hs_, kt_, cb_)                                                 \
    do {                                                                              \
        unsigned dbase = hx_u32 + (unsigned)((cb_) * (KT * PADA * 4));                \
        int kt0 = (kt_) * KT;                                                         \
        _Pragma("unroll")                                                             \
        for (int u = tid; u < KT * 16; u += TTHR) {                                   \
            int row = u >> 4, ch = u & 15;                                            \
            int j = kt0 + row;                                                        \
            const float* s = ((j < 256) ? ((xs_) + j * NN)                            \
                                        : ((hs_) + (j - 256) * NN)) +                 \
                             nbase + ch * 4;                                          \
            unsigned d = dbase + (unsigned)(row * (PADA * 4) + ch * 16);              \
            asm volatile("cp.async.cg.shared.global [%0], [%1], 16;" ::"r"(d),        \
                         "l"(s));                                                     \
        }                                                                             \
        asm volatile("cp.async.commit_group;");                                      \
    } while (0)

// compute one staged tile into the 64 packed accumulators
#define COMPUTE_TILE(kt_, cb_)                                                        \
    do {                                                                              \
        const float* hxb = hxs + (cb_) * (KT * PADA);                                 \
        _Pragma("unroll")                                                             \
        for (int jj = 0; jj < 6; jj++) {                                              \
            const int kl = klane + 16 * jj;                                           \
            const int jg = (kt_) * KT + kl;                                           \
            const ulonglong2* ap = (const ulonglong2*)(hxb + kl * PADA + ng * 16);    \
            ulonglong2 a0 = ap[0], a1 = ap[1], a2 = ap[2], a3 = ap[3];                \
            unsigned long long av[8] = {a0.x, a0.y, a1.x, a1.y,                       \
                                        a2.x, a2.y, a3.x, a3.y};                      \
            const float4* wp = (const float4*)(Wsm + jg * 32 + cg * 8);               \
            float4 w0 = wp[0], w1 = wp[1];                                            \
            unsigned long long wpk[2][4];                                             \
            wpk[0][0] = pack2(w0.x); wpk[0][1] = pack2(w0.y);                         \
            wpk[0][2] = pack2(w0.z); wpk[0][3] = pack2(w0.w);                         \
            wpk[1][0] = pack2(w1.x); wpk[1][1] = pack2(w1.y);                         \
            wpk[1][2] = pack2(w1.z); wpk[1][3] = pack2(w1.w);                         \
            _Pragma("unroll")                                                         \
            for (int g = 0; g < 4; g++)                                               \
                _Pragma("unroll")                                                     \
                for (int j = 0; j < 8; j++) {                                         \
                    ffma2(acc[g * 16 + j * 2 + 0], av[j], wpk[0][g]);                 \
                    ffma2(acc[g * 16 + j * 2 + 1], av[j], wpk[1][g]);                 \
                }                                                                     \
        }                                                                             \
    } while (0)

#define WAITG1 asm volatile("cp.async.wait_group 1;")

extern __shared__ char smem_raw[];

__global__ void __launch_bounds__(TTHR, 1)
lstm_persistent(const int* __restrict__ X, const float* __restrict__ E,
                const float* __restrict__ Wi, const float* __restrict__ bi,
                const float* __restrict__ Wf, const float* __restrict__ bf,
                const float* __restrict__ Wo, const float* __restrict__ bo,
                const float* __restrict__ Wh, const float* __restrict__ bh,
                float* __restrict__ out) {
    float* Wsm = (float*)(smem_raw + SM_W);
    float* hxs = (float*)(smem_raw + SM_HX);
    unsigned long long* red = (unsigned long long*)(smem_raw + SM_RED);
    __shared__ int toks[NN];

    const int tid   = threadIdx.x;
    const int warp  = tid >> 5;
    const int lane  = tid & 31;
    const int kp_lo = lane >> 4;
    const int ng    = (lane >> 2) & 3;
    const int cg    = lane & 3;

    const int colgrp = blockIdx.x >> 1;
    const int nh     = blockIdx.x & 1;
    const int colbase = colgrp * 8;
    const int nbase   = nh * 64;
    const int grp     = blockIdx.x >> 3;   // arrival group (16 groups of 8)

    // ---- reset per-launch counters (replay safety) ----
    if (blockIdx.x == 0 && tid < 32) {
        if (tid < 16) g_cnt1[tid * 32] = 0u;
        if (tid == 16) g_cnt2 = 0u;
        if (tid == 17) g_gen = 0u;
    }

    // ---- load weights into smem, PERMUTED k order: j<256 -> x(512+j), else h(j-256) ----
    for (int i = tid; i < DD * 8; i += TTHR) {
        int j = i >> 3, c = i & 7;
        int k = (j < 256) ? (512 + j) : (j - 256);
        int col = colbase + c;
        float* w = Wsm + j * 32 + c * 4;
        w[0] = Wi[k * HIDDEN + col];
        w[1] = Wf[k * HIDDEN + col];
        w[2] = Wo[k * HIDDEN + col];
        w[3] = Wh[k * HIDDEN + col];
    }

    // ---- precompute transposed embeddings (each CTA handles 4 timesteps) ----
    for (int tt = 0; tt < 4; tt++) {
        int t = blockIdx.x * 4 + tt;
        __syncthreads();
        if (tid < NN) toks[tid] = X[tid * LL + t];
        __syncthreads();
        float* dst = g_xT[t];
        for (int i = tid; i < EMBED * NN; i += TTHR) {
            int e = i >> 7, n = i & 127;
            dst[i] = E[toks[n] * EMBED + e];
        }
    }

    // ---- zero initial h (buffer 0) ----
    for (int i = tid; i < 512; i += TTHR) g_hT[0][blockIdx.x * 512 + i] = 0.0f;

    // ---- epilogue role ----
    const int ce    = tid & 7;
    const int np_e  = tid >> 3;
    const int col_e = colbase + ce;
    const int cge = ce >> 1, cce = ce & 1;
    const int nge = np_e >> 3, je = np_e & 7;
    const int slot_e = nge * 4 + cge;
    const float b_i = bi[col_e], b_f = bf[col_e], b_o = bo[col_e], b_g = bh[col_e];
    float cs0 = 0.0f, cs1 = 0.0f;

    entrybarrier();   // embeds + h0 + counter resets globally visible

    const unsigned hx_u32 = (unsigned)__cvta_generic_to_shared(hxs);
    const int klane  = warp * 2 + kp_lo;
    const int slot_w = ng * 4 + cg;

    // prologue: x tiles 0,1 of step 0
    COPY_TILE(g_xT[0], g_hT[0], 0, 0);
    COPY_TILE(g_xT[0], g_hT[0], 1, 1);

    for (int t = 0; t < LL; t++) {
        const int p = t & 1;
        const float* hsrc = g_hT[p];
        const float* xsrc = g_xT[t];

        unsigned long long acc[64];
#pragma unroll
        for (int r = 0; r < 64; r++) acc[r] = 0ull;

        // tile 0 (pure x)
        WAITG1; __syncthreads();
        COMPUTE_TILE(0, 0);
        __syncthreads();
        // h_{t-1} must be published before we read it (tile 2 onward)
        if ((int)g_gen < t) {
            while ((int)g_gen < t) { __nanosleep(64); }
        }
        COPY_TILE(xsrc, hsrc, 2, 0);

        // tile 1 (pure x)
        WAITG1; __syncthreads();
        COMPUTE_TILE(1, 1);
        __syncthreads();
        COPY_TILE(xsrc, hsrc, 3, 1);

        // tiles 2..5
        WAITG1; __syncthreads();
        COMPUTE_TILE(2, 0);
        __syncthreads();
        COPY_TILE(xsrc, hsrc, 4, 0);

        WAITG1; __syncthreads();
        COMPUTE_TILE(3, 1);
        __syncthreads();
        COPY_TILE(xsrc, hsrc, 5, 1);

        WAITG1; __syncthreads();
        COMPUTE_TILE(4, 0);
        __syncthreads();
        COPY_TILE(xsrc, hsrc, 6, 0);

        WAITG1; __syncthreads();
        COMPUTE_TILE(5, 1);
        __syncthreads();
        COPY_TILE(xsrc, hsrc, 7, 1);

        // tile 6; afterwards prefetch next step's x tile 0
        WAITG1; __syncthreads();
        COMPUTE_TILE(6, 0);
        __syncthreads();
        if (t + 1 < LL) COPY_TILE(g_xT[t + 1], hsrc, 0, 0);

        // tile 7; afterwards prefetch next step's x tile 1
        WAITG1; __syncthreads();
        COMPUTE_TILE(7, 1);
        __syncthreads();
        if (t + 1 < LL) COPY_TILE(g_xT[t + 1], hsrc, 1, 1);

        // ---- reduce 2 k-phases within warp ----
#pragma unroll
        for (int r = 0; r < 64; r++) {
            unsigned long long o = __shfl_xor_sync(0xffffffffu, acc[r], 16);
            acc[r] = add2(acc[r], o);
        }
        if (kp_lo == 0) {
#pragma unroll
            for (int r = 0; r < 64; r++)
                red[(warp * 64 + r) * 17 + slot_w] = acc[r];
        }
        __syncthreads();

        // ---- gather 8 warp partials + gates + state update ----
        unsigned long long s[4];
#pragma unroll
        for (int g = 0; g < 4; g++) {
            int r = g * 16 + je * 2 + cce;
            unsigned long long v = red[r * 17 + slot_e];
#pragma unroll
            for (int pp = 1; pp < 8; pp++)
                v = add2(v, red[(pp * 64 + r) * 17 + slot_e]);
            s[g] = v;
        }
        float2 vi = unpack64(s[0]), vf = unpack64(s[1]);
        float2 vo = unpack64(s[2]), vg = unpack64(s[3]);
        float i0 = sigmoidf_fast(vi.x + b_i), i1 = sigmoidf_fast(vi.y + b_i);
        float f0 = sigmoidf_fast(vf.x + b_f), f1 = sigmoidf_fast(vf.y + b_f);
        float o0 = sigmoidf_fast(vo.x + b_o), o1 = sigmoidf_fast(vo.y + b_o);
        float g0 = tanhf_fast(vg.x + b_g),    g1 = tanhf_fast(vg.y + b_g);

        cs0 = f0 * cs0 + i0 * g0;
        cs1 = f1 * cs1 + i1 * g1;
        float h0 = o0 * tanhf_fast(cs0);
        float h1 = o1 * tanhf_fast(cs1);

        *(float2*)(g_hT[p ^ 1] + col_e * NN + nbase + 2 * np_e) =
            make_float2(h0, h1);

        if (t == LL - 1) {
            out[(nbase + 2 * np_e) * HIDDEN + col_e]     = h0;
            out[(nbase + 2 * np_e + 1) * HIDDEN + col_e] = h1;
        }

        // ---- publish h_t: per-thread fence, then two-level arrival (no wait!) ----
        __threadfence();
        __syncthreads();
        if (tid == 0) {
            unsigned o1 = atomicAdd(&g_cnt1[grp * 32], 1u);
            if ((o1 & 7u) == 7u) {
                unsigned o2 = atomicAdd(&g_cnt2, 1u);
                if ((o2 & 15u) == 15u) {
                    __threadfence();
                    g_gen = (unsigned)(t + 1);
                }
            }
        }
    }
}

// ---------------- launch ----------------
extern "C" void kernel_launch(void* const* d_in, const int* in_sizes, int n_in,
                              void* d_out, int out_size) {
    const int*   X  = (const int*)d_in[0];
    const float* E  = (const float*)d_in[1];
    const float* Wi = (const float*)d_in[2];
    const float* bi = (const float*)d_in[3];
    const float* Wf = (const float*)d_in[4];
    const float* bf = (const float*)d_in[5];
    const float* Wo = (const float*)d_in[6];
    const float* bo = (const float*)d_in[7];
    const float* Wh = (const float*)d_in[8];
    const float* bh = (const float*)d_in[9];
    float* out = (float*)d_out;

    cudaFuncSetAttribute(lstm_persistent,
                         cudaFuncAttributeMaxDynamicSharedMemorySize, SM_TOT);

    lstm_persistent<<<GCTAS, TTHR, SM_TOT>>>(X, E, Wi, bi, Wf, bf, Wo, bo, Wh, bh,
                                             out);
}

// round 7
// speedup vs baseline: 3.6258x; 1.3224x over previous
#include <cuda_runtime.h>
#include <cuda_bf16.h>
#include <cstdint>

#define NN 128
#define LL 512
#define HIDDEN 512
#define EMBED 256
#define GCTAS 128
#define TTHR 256

// CTA = (mslice: 32 batch rows) x (colgrp: 16 h-cols -> 64 gate-cols)
// K = 768 logical j: [0,256) -> x (k=512+j), [256,768) -> h (k=j-256)
// 12 k-tiles of 64; tiles 0-3 pure x.

// smem: W hi/lo resident, rows n=0..63 (n = hcol_local*4 + gate), stride 1552B
#define WSTR 1552
#define SM_WH 0
#define SM_WL 99328          // 64*1552
#define SM_A  198656         // A tiles: [buf2][split2][32 rows x 144B]
#define ASTR  144
#define ASPL  4608           // 32*144
#define ABUF  9216
#define SM_TOT 217088        // 198656 + 2*9216

__device__ __nv_bfloat16 g_hh[2][NN * HIDDEN];
__device__ __nv_bfloat16 g_hl[2][NN * HIDDEN];
__device__ __nv_bfloat16 g_xh[LL][NN * EMBED];
__device__ __nv_bfloat16 g_xl[LL][NN * EMBED];
__device__ unsigned g_ecnt;
__device__ volatile unsigned g_egen;
__device__ unsigned g_cnt;
__device__ volatile unsigned g_gen;   // == t+1 when h_t published

__device__ __forceinline__ uint32_t smem_u32(const void* p) {
    uint32_t a;
    asm("{ .reg .u64 t; cvta.to.shared.u64 t, %1; cvt.u32.u64 %0, t; }" : "=r"(a) : "l"(p));
    return a;
}
__device__ __forceinline__ float sigf(float x) {
    return __fdividef(1.0f, 1.0f + __expf(-x));
}
__device__ __forceinline__ float tanhf_fast(float x) {
    return __fdividef(2.0f, 1.0f + __expf(-2.0f * x)) - 1.0f;
}

#define LDSM4(r0, r1, r2, r3, ad)                                            \
    asm volatile("ldmatrix.sync.aligned.m8n8.x4.shared.b16 {%0,%1,%2,%3}, [%4];" \
                 : "=r"(r0), "=r"(r1), "=r"(r2), "=r"(r3) : "r"(ad))
#define LDSM2(r0, r1, ad)                                                    \
    asm volatile("ldmatrix.sync.aligned.m8n8.x2.shared.b16 {%0,%1}, [%2];"   \
                 : "=r"(r0), "=r"(r1) : "r"(ad))

__device__ __forceinline__ void mma16816(float* d, uint32_t a0, uint32_t a1,
                                         uint32_t a2, uint32_t a3, uint32_t b0,
                                         uint32_t b1) {
    asm volatile(
        "mma.sync.aligned.m16n8k16.row.col.f32.bf16.bf16.f32 "
        "{%0,%1,%2,%3},{%4,%5,%6,%7},{%8,%9},{%0,%1,%2,%3};"
        : "+f"(d[0]), "+f"(d[1]), "+f"(d[2]), "+f"(d[3])
        : "r"(a0), "r"(a1), "r"(a2), "r"(a3), "r"(b0), "r"(b1));
}

__device__ __forceinline__ void entrybarrier() {
    __syncthreads();
    if (threadIdx.x == 0) {
        unsigned my = g_egen;
        __threadfence();
        unsigned old = atomicAdd(&g_ecnt, 1u);
        if (old == (GCTAS - 1)) {
            atomicExch(&g_ecnt, 0u);
            __threadfence();
            g_egen = my + 1u;
        } else {
            while (g_egen == my) { __nanosleep(64); }
        }
        __threadfence();
    }
    __syncthreads();
}

// stage one k64 tile (hi+lo, 32 rows x 128B each) into buffer b
__device__ __forceinline__ void stage(int tid, uint32_t su, int b, const char* ah,
                                      const char* al, int astr) {
    uint32_t dstb = su + SM_A + b * ABUF;
#pragma unroll
    for (int u = tid; u < 512; u += TTHR) {
        int split = u >> 8, row = (u >> 3) & 31, ch = u & 7;
        const char* src = (split ? al : ah) + row * astr + ch * 16;
        uint32_t dst = dstb + split * ASPL + row * ASTR + ch * 16;
        asm volatile("cp.async.cg.shared.global [%0], [%1], 16;" ::"r"(dst), "l"(src));
    }
    asm volatile("cp.async.commit_group;" ::: "memory");
}

extern __shared__ char smem_raw[];

__global__ void __launch_bounds__(TTHR, 1)
lstm_hmma(const int* __restrict__ X, const float* __restrict__ E,
          const float* __restrict__ Wi, const float* __restrict__ bi,
          const float* __restrict__ Wf, const float* __restrict__ bf,
          const float* __restrict__ Wo, const float* __restrict__ bo,
          const float* __restrict__ Wh, const float* __restrict__ bh,
          float* __restrict__ out) {
    __shared__ int toks[NN];
    __shared__ float s_bias[64];

    const int tid = threadIdx.x;
    const int warp = tid >> 5;
    const int lane = tid & 31;
    const int q = lane & 3;
    const int rb = lane >> 2;
    const uint32_t su = smem_u32(smem_raw);
    char* dyn = smem_raw;

    const int mslice = blockIdx.x & 3;
    const int colgrp = blockIdx.x >> 2;
    const int mbase = mslice * 32;
    const int colbase = colgrp * 16;

    if (blockIdx.x == 0 && tid == 0) { g_cnt = 0u; g_gen = 0u; }

    // ---- weights resident in smem (hi + lo), rows n = hcol_local*4+gate, k = logical j ----
    for (int n = 0; n < 64; n++) {
        int hc = colbase + (n >> 2), gate = n & 3;
        const float* Wg = (gate == 0) ? Wi : (gate == 1) ? Wf : (gate == 2) ? Wo : Wh;
        for (int j = tid; j < 768; j += TTHR) {
            int k = (j < 256) ? (512 + j) : (j - 256);
            float w = Wg[k * HIDDEN + hc];
            __nv_bfloat16 hi = __float2bfloat16(w);
            *(__nv_bfloat16*)(dyn + SM_WH + n * WSTR + j * 2) = hi;
            *(__nv_bfloat16*)(dyn + SM_WL + n * WSTR + j * 2) =
                __float2bfloat16(w - __bfloat162float(hi));
        }
    }
    if (tid < 64) {
        int gate = tid & 3;
        const float* Bg = (gate == 0) ? bi : (gate == 1) ? bf : (gate == 2) ? bo : bh;
        s_bias[tid] = Bg[colbase + (tid >> 2)];
    }

    // ---- embeddings (hi/lo), 4 timesteps per CTA, layout [t][m][e] ----
    for (int tt = 0; tt < 4; tt++) {
        int t = blockIdx.x * 4 + tt;
        __syncthreads();
        if (tid < NN) toks[tid] = X[tid * LL + t];
        __syncthreads();
        __nv_bfloat16* dh = g_xh[t];
        __nv_bfloat16* dl = g_xl[t];
        for (int i = tid; i < NN * EMBED; i += TTHR) {
            float v = E[(size_t)toks[i >> 8] * EMBED + (i & 255)];
            __nv_bfloat16 hi = __float2bfloat16(v);
            dh[i] = hi;
            dl[i] = __float2bfloat16(v - __bfloat162float(hi));
        }
    }
    // ---- zero initial h (buffer 0) ----
    {
        unsigned* zh = (unsigned*)g_hh[0];
        unsigned* zl = (unsigned*)g_hl[0];
        for (int i = tid; i < 256; i += TTHR) {
            zh[blockIdx.x * 256 + i] = 0u;
            zl[blockIdx.x * 256 + i] = 0u;
        }
    }

    // per-thread constant ldmatrix addresses
    const uint32_t a_off = (uint32_t)((lane & 15) * ASTR + (lane >> 4) * 16);
    const uint32_t b_off = (uint32_t)((warp * 8 + (lane & 7)) * WSTR + ((lane >> 3) & 1) * 16);
    const uint32_t bW_h = su + SM_WH + b_off;
    const uint32_t bW_l = su + SM_WL + b_off;
    const float b0v = s_bias[warp * 8 + q * 2];
    const float b1v = s_bias[warp * 8 + q * 2 + 1];

    float cs[4] = {0.0f, 0.0f, 0.0f, 0.0f};

    entrybarrier();

    // prologue: stage tile 0 of step 0 (pure x) into buf 0
    stage(tid, su, 0, (const char*)g_xh[0] + mbase * 512,
          (const char*)g_xl[0] + mbase * 512, 512);

    for (int t = 0; t < LL; t++) {
        float D0[2][4], D1[2][4];
#pragma unroll
        for (int i = 0; i < 4; i++) {
            D0[0][i] = D0[1][i] = D1[0][i] = D1[1][i] = 0.0f;
        }

#pragma unroll 1
        for (int tile = 0; tile < 12; tile++) {
            // stage next tile (possibly next step's tile 0)
            int nt = tile + 1, ns = t;
            if (nt == 12) { nt = 0; ns = t + 1; }
            int staged = 0;
            if (ns < LL) {
                if (nt == 4) {   // first h-tile of step ns: h_{ns-1} must be published
                    if (tid == 0) {
                        while (g_gen < (unsigned)ns) { __nanosleep(32); }
                    }
                    __syncthreads();
                }
                const char *ah, *al;
                int astr;
                if (nt < 4) {
                    ah = (const char*)g_xh[ns] + mbase * 512 + nt * 128;
                    al = (const char*)g_xl[ns] + mbase * 512 + nt * 128;
                    astr = 512;
                } else {
                    int hp = ns & 1;   // h_{ns-1} lives in buffer ns&1
                    ah = (const char*)g_hh[hp] + mbase * 1024 + (nt - 4) * 128;
                    al = (const char*)g_hl[hp] + mbase * 1024 + (nt - 4) * 128;
                    astr = 1024;
                }
                stage(tid, su, nt & 1, ah, al, astr);
                staged = 1;
            }
            if (staged)
                asm volatile("cp.async.wait_group 1;" ::: "memory");
            else
                asm volatile("cp.async.wait_group 0;" ::: "memory");
            __syncthreads();

            // ---- compute tile ----
            const uint32_t Ah = su + SM_A + (tile & 1) * ABUF + a_off;
#pragma unroll
            for (int kk = 0; kk < 4; kk++) {
                const uint32_t kb = (uint32_t)(tile * 128 + kk * 32);
                uint32_t bh0, bh1, bl0, bl1;
                LDSM2(bh0, bh1, bW_h + kb);
                LDSM2(bl0, bl1, bW_l + kb);
#pragma unroll
                for (int mt = 0; mt < 2; mt++) {
                    uint32_t ab = Ah + mt * (16 * ASTR) + kk * 32;
                    uint32_t a0, a1, a2, a3, l0, l1, l2, l3;
                    LDSM4(a0, a1, a2, a3, ab);
                    LDSM4(l0, l1, l2, l3, ab + ASPL);
                    mma16816(D0[mt], a0, a1, a2, a3, bh0, bh1);
                    mma16816(D1[mt], l0, l1, l2, l3, bh0, bh1);
                    mma16816(D1[mt], a0, a1, a2, a3, bl0, bl1);
                }
            }
            __syncthreads();
        }

        // ---- epilogue: gates + state update + publish h ----
        const int pn = (t & 1) ^ 1;
#pragma unroll
        for (int s = 0; s < 4; s++) {
            const int mt = s >> 1, r2 = s & 1;
            float a0 = D0[mt][r2 * 2 + 0] + D1[mt][r2 * 2 + 0] + b0v;
            float a1 = D0[mt][r2 * 2 + 1] + D1[mt][r2 * 2 + 1] + b1v;
            float p0 = __shfl_xor_sync(0xffffffffu, a0, 1);
            float p1 = __shfl_xor_sync(0xffffffffu, a1, 1);
            float iv, fv, ov, gv;
            if (q & 1) { iv = p0; fv = p1; ov = a0; gv = a1; }
            else       { iv = a0; fv = a1; ov = p0; gv = p1; }
            iv = sigf(iv);
            fv = sigf(fv);
            ov = sigf(ov);
            gv = tanhf_fast(gv);
            cs[s] = fv * cs[s] + iv * gv;
            float hv = ov * tanhf_fast(cs[s]);
            if (!(q & 1)) {
                int m = mbase + mt * 16 + rb + r2 * 8;
                int hc = colbase + 2 * warp + (q >> 1);
                __nv_bfloat16 hi = __float2bfloat16(hv);
                g_hh[pn][m * HIDDEN + hc] = hi;
                g_hl[pn][m * HIDDEN + hc] =
                    __float2bfloat16(hv - __bfloat162float(hi));
                if (t == LL - 1) out[m * HIDDEN + hc] = hv;
            }
        }
        __threadfence();
        __syncthreads();
        if (tid == 0) {
            unsigned old = atomicAdd(&g_cnt, 1u);
            if ((old & 127u) == 127u) {
                __threadfence();
                g_gen = (unsigned)(t + 1);
            }
        }
    }
}

extern "C" void kernel_launch(void* const* d_in, const int* in_sizes, int n_in,
                              void* d_out, int out_size) {
    const int* X = (const int*)d_in[0];
    const float* E = (const float*)d_in[1];
    const float* Wi = (const float*)d_in[2];
    const float* bi = (const float*)d_in[3];
    const float* Wf = (const float*)d_in[4];
    const float* bf = (const float*)d_in[5];
    const float* Wo = (const float*)d_in[6];
    const float* bo = (const float*)d_in[7];
    const float* Wh = (const float*)d_in[8];
    const float* bh = (const float*)d_in[9];
    float* out = (float*)d_out;

    cudaFuncSetAttribute(lstm_hmma, cudaFuncAttributeMaxDynamicSharedMemorySize,
                         SM_TOT);
    lstm_hmma<<<GCTAS, TTHR, SM_TOT>>>(X, E, Wi, bi, Wf, bf, Wo, bo, Wh, bh, out);
}

// round 8
// speedup vs baseline: 3.7625x; 1.0377x over previous
#include <cuda_runtime.h>
#include <cuda_bf16.h>
#include <cstdint>

#define NN 128
#define LL 512
#define HIDDEN 512
#define EMBED 256
#define GCTAS 128
#define TTHR 512

// CTA = (mslice: 32 batch rows) x (colgrp: 16 h-cols -> 64 gate-cols)
// 16 warps: wn = warp&7 (N-group of 8 gate-cols), mg = warp>>3 (M-group of 16 rows)
// K = 768 logical j: [0,256) -> x (k=512+j), [256,768) -> h (k=j-256)
// 12 k64 tiles; tiles 0-3 pure x. Buffer ring of 3 (12 % 3 == 0 -> buf = tile%3).

#define WSTR 1552
#define SM_WH 0
#define SM_WL 99328          // 64*1552
#define SM_A  198656         // A tiles: [buf3][split2][32 rows x 144B]
#define ASTR  144
#define ASPL  4608           // 32*144
#define ABUF  9216
#define SM_TOT 226304        // 198656 + 3*9216

__device__ __nv_bfloat16 g_hh[2][NN * HIDDEN];
__device__ __nv_bfloat16 g_hl[2][NN * HIDDEN];
__device__ __nv_bfloat16 g_xh[LL][NN * EMBED];
__device__ __nv_bfloat16 g_xl[LL][NN * EMBED];
__device__ unsigned g_ecnt;
__device__ volatile unsigned g_egen;
__device__ unsigned g_cnt;
__device__ volatile unsigned g_gen;   // == t+1 when h_t published

__device__ __forceinline__ uint32_t smem_u32(const void* p) {
    uint32_t a;
    asm("{ .reg .u64 t; cvta.to.shared.u64 t, %1; cvt.u32.u64 %0, t; }" : "=r"(a) : "l"(p));
    return a;
}
__device__ __forceinline__ float sigf(float x) {
    return __fdividef(1.0f, 1.0f + __expf(-x));
}
__device__ __forceinline__ float tanhf_fast(float x) {
    return __fdividef(2.0f, 1.0f + __expf(-2.0f * x)) - 1.0f;
}

#define LDSM4(r0, r1, r2, r3, ad)                                            \
    asm volatile("ldmatrix.sync.aligned.m8n8.x4.shared.b16 {%0,%1,%2,%3}, [%4];" \
                 : "=r"(r0), "=r"(r1), "=r"(r2), "=r"(r3) : "r"(ad))
#define LDSM2(r0, r1, ad)                                                    \
    asm volatile("ldmatrix.sync.aligned.m8n8.x2.shared.b16 {%0,%1}, [%2];"   \
                 : "=r"(r0), "=r"(r1) : "r"(ad))

__device__ __forceinline__ void mma16816(float* d, uint32_t a0, uint32_t a1,
                                         uint32_t a2, uint32_t a3, uint32_t b0,
                                         uint32_t b1) {
    asm volatile(
        "mma.sync.aligned.m16n8k16.row.col.f32.bf16.bf16.f32 "
        "{%0,%1,%2,%3},{%4,%5,%6,%7},{%8,%9},{%0,%1,%2,%3};"
        : "+f"(d[0]), "+f"(d[1]), "+f"(d[2]), "+f"(d[3])
        : "r"(a0), "r"(a1), "r"(a2), "r"(a3), "r"(b0), "r"(b1));
}

__device__ __forceinline__ void entrybarrier() {
    __syncthreads();
    if (threadIdx.x == 0) {
        unsigned my = g_egen;
        __threadfence();
        unsigned old = atomicAdd(&g_ecnt, 1u);
        if (old == (GCTAS - 1)) {
            atomicExch(&g_ecnt, 0u);
            __threadfence();
            g_egen = my + 1u;
        } else {
            while (g_egen == my) { __nanosleep(64); }
        }
        __threadfence();
    }
    __syncthreads();
}

// stage one k64 tile (hi+lo, 32 rows x 128B each) into buffer b: 512 x 16B = 1/thread
__device__ __forceinline__ void stage(int tid, uint32_t su, int b, const char* ah,
                                      const char* al, int astr) {
    uint32_t dstb = su + SM_A + b * ABUF;
    int split = tid >> 8, row = (tid >> 3) & 31, ch = tid & 7;
    const char* src = (split ? al : ah) + row * astr + ch * 16;
    uint32_t dst = dstb + split * ASPL + row * ASTR + ch * 16;
    asm volatile("cp.async.cg.shared.global [%0], [%1], 16;" ::"r"(dst), "l"(src));
    asm volatile("cp.async.commit_group;" ::: "memory");
}

extern __shared__ char smem_raw[];

__global__ void __launch_bounds__(TTHR, 1)
lstm_hmma(const int* __restrict__ X, const float* __restrict__ E,
          const float* __restrict__ Wi, const float* __restrict__ bi,
          const float* __restrict__ Wf, const float* __restrict__ bf,
          const float* __restrict__ Wo, const float* __restrict__ bo,
          const float* __restrict__ Wh, const float* __restrict__ bh,
          float* __restrict__ out) {
    __shared__ int toks[NN];
    __shared__ float s_bias[64];

    const int tid = threadIdx.x;
    const int warp = tid >> 5;
    const int lane = tid & 31;
    const int q = lane & 3;
    const int rb = lane >> 2;
    const int wn = warp & 7;     // N-group
    const int mg = warp >> 3;    // M-group
    const uint32_t su = smem_u32(smem_raw);
    char* dyn = smem_raw;

    const int mslice = blockIdx.x & 3;
    const int colgrp = blockIdx.x >> 2;
    const int mbase = mslice * 32;
    const int colbase = colgrp * 16;

    if (blockIdx.x == 0 && tid == 0) { g_cnt = 0u; g_gen = 0u; }

    // ---- weights resident in smem (hi + lo), rows n = hcol_local*4+gate ----
    for (int n = 0; n < 64; n++) {
        int hc = colbase + (n >> 2), gate = n & 3;
        const float* Wg = (gate == 0) ? Wi : (gate == 1) ? Wf : (gate == 2) ? Wo : Wh;
        for (int j = tid; j < 768; j += TTHR) {
            int k = (j < 256) ? (512 + j) : (j - 256);
            float w = Wg[k * HIDDEN + hc];
            __nv_bfloat16 hi = __float2bfloat16(w);
            *(__nv_bfloat16*)(dyn + SM_WH + n * WSTR + j * 2) = hi;
            *(__nv_bfloat16*)(dyn + SM_WL + n * WSTR + j * 2) =
                __float2bfloat16(w - __bfloat162float(hi));
        }
    }
    if (tid < 64) {
        int gate = tid & 3;
        const float* Bg = (gate == 0) ? bi : (gate == 1) ? bf : (gate == 2) ? bo : bh;
        s_bias[tid] = Bg[colbase + (tid >> 2)];
    }

    // ---- embeddings (hi/lo), 4 timesteps per CTA, layout [t][m][e] ----
    for (int tt = 0; tt < 4; tt++) {
        int t = blockIdx.x * 4 + tt;
        __syncthreads();
        if (tid < NN) toks[tid] = X[tid * LL + t];
        __syncthreads();
        __nv_bfloat16* dh = g_xh[t];
        __nv_bfloat16* dl = g_xl[t];
        for (int i = tid; i < NN * EMBED; i += TTHR) {
            float v = E[(size_t)toks[i >> 8] * EMBED + (i & 255)];
            __nv_bfloat16 hi = __float2bfloat16(v);
            dh[i] = hi;
            dl[i] = __float2bfloat16(v - __bfloat162float(hi));
        }
    }
    // ---- zero initial h (buffer 0) ----
    if (tid < 256) {
        ((unsigned*)g_hh[0])[blockIdx.x * 256 + tid] = 0u;
        ((unsigned*)g_hl[0])[blockIdx.x * 256 + tid] = 0u;
    }

    // per-thread constant ldmatrix addresses
    const uint32_t a_off =
        (uint32_t)(mg * (16 * ASTR) + (lane & 15) * ASTR + (lane >> 4) * 16);
    const uint32_t b_off =
        (uint32_t)((wn * 8 + (lane & 7)) * WSTR + ((lane >> 3) & 1) * 16);
    const uint32_t bW_h = su + SM_WH + b_off;
    const uint32_t bW_l = su + SM_WL + b_off;
    const float b0v = s_bias[wn * 8 + q * 2];
    const float b1v = s_bias[wn * 8 + q * 2 + 1];

    float cs[2] = {0.0f, 0.0f};

    entrybarrier();

    // prologue: stage tiles 0,1 of step 0 (pure x) into bufs 0,1
    stage(tid, su, 0, (const char*)g_xh[0] + mbase * 512,
          (const char*)g_xl[0] + mbase * 512, 512);
    stage(tid, su, 1, (const char*)g_xh[0] + mbase * 512 + 128,
          (const char*)g_xl[0] + mbase * 512 + 128, 512);

    for (int t = 0; t < LL; t++) {
        float D0[4], D1a[4], D1b[4];
#pragma unroll
        for (int i = 0; i < 4; i++) D0[i] = D1a[i] = D1b[i] = 0.0f;

#pragma unroll 1
        for (int tile = 0; tile < 12; tile++) {
            // wait for tile's data (one group may remain outstanding)
            if (t == LL - 1 && tile == 11)
                asm volatile("cp.async.wait_group 0;" ::: "memory");
            else
                asm volatile("cp.async.wait_group 1;" ::: "memory");
            __syncthreads();   // tile arrived everywhere; tile-1 fully computed

            // stage tile+2 (possibly next step)
            int nt = tile + 2, ns = t;
            if (nt >= 12) { nt -= 12; ns++; }
            if (ns < LL) {
                if (nt == 4) {   // first h-tile of step ns: wait h_{ns-1} published
                    while (g_gen < (unsigned)ns) { __nanosleep(32); }
                }
                const char *ah, *al;
                int astr;
                if (nt < 4) {
                    ah = (const char*)g_xh[ns] + mbase * 512 + nt * 128;
                    al = (const char*)g_xl[ns] + mbase * 512 + nt * 128;
                    astr = 512;
                } else {
                    int hp = ns & 1;
                    ah = (const char*)g_hh[hp] + mbase * 1024 + (nt - 4) * 128;
                    al = (const char*)g_hl[hp] + mbase * 1024 + (nt - 4) * 128;
                    astr = 1024;
                }
                stage(tid, su, nt % 3, ah, al, astr);
            }

            // ---- compute tile (buf = tile%3) ----
            const uint32_t Ah = su + SM_A + (tile % 3) * ABUF + a_off;
#pragma unroll
            for (int kk = 0; kk < 4; kk++) {
                const uint32_t kb = (uint32_t)(tile * 128 + kk * 32);
                uint32_t bh0, bh1, bl0, bl1;
                LDSM2(bh0, bh1, bW_h + kb);
                LDSM2(bl0, bl1, bW_l + kb);
                uint32_t ab = Ah + kk * 32;
                uint32_t a0, a1, a2, a3, l0, l1, l2, l3;
                LDSM4(a0, a1, a2, a3, ab);
                LDSM4(l0, l1, l2, l3, ab + ASPL);
                mma16816(D0, a0, a1, a2, a3, bh0, bh1);
                mma16816(D1a, l0, l1, l2, l3, bh0, bh1);
                mma16816(D1b, a0, a1, a2, a3, bl0, bl1);
            }
        }

        // ---- epilogue: gates + state update + publish h ----
        const int pn = (t & 1) ^ 1;
#pragma unroll
        for (int s = 0; s < 2; s++) {
            float a0 = D0[s * 2 + 0] + D1a[s * 2 + 0] + D1b[s * 2 + 0] + b0v;
            float a1 = D0[s * 2 + 1] + D1a[s * 2 + 1] + D1b[s * 2 + 1] + b1v;
            float p0 = __shfl_xor_sync(0xffffffffu, a0, 1);
            float p1 = __shfl_xor_sync(0xffffffffu, a1, 1);
            float iv, fv, ov, gv;
            if (q & 1) { iv = p0; fv = p1; ov = a0; gv = a1; }
            else       { iv = a0; fv = a1; ov = p0; gv = p1; }
            iv = sigf(iv);
            fv = sigf(fv);
            ov = sigf(ov);
            gv = tanhf_fast(gv);
            cs[s] = fv * cs[s] + iv * gv;
            float hv = ov * tanhf_fast(cs[s]);
            if (!(q & 1)) {
                int m = mbase + mg * 16 + rb + s * 8;
                int hc = colbase + wn * 2 + (q >> 1);
                __nv_bfloat16 hi = __float2bfloat16(hv);
                g_hh[pn][m * HIDDEN + hc] = hi;
                g_hl[pn][m * HIDDEN + hc] =
                    __float2bfloat16(hv - __bfloat162float(hi));
                if (t == LL - 1) out[m * HIDDEN + hc] = hv;
            }
        }
        __threadfence();
        __syncthreads();
        if (tid == 0) {
            unsigned old = atomicAdd(&g_cnt, 1u);
            if ((old & 127u) == 127u) {
                __threadfence();
                g_gen = (unsigned)(t + 1);
            }
        }
    }
}

extern "C" void kernel_launch(void* const* d_in, const int* in_sizes, int n_in,
                              void* d_out, int out_size) {
    const int* X = (const int*)d_in[0];
    const float* E = (const float*)d_in[1];
    const float* Wi = (const float*)d_in[2];
    const float* bi = (const float*)d_in[3];
    const float* Wf = (const float*)d_in[4];
    const float* bf = (const float*)d_in[5];
    const float* Wo = (const float*)d_in[6];
    const float* bo = (const float*)d_in[7];
    const float* Wh = (const float*)d_in[8];
    const float* bh = (const float*)d_in[9];
    float* out = (float*)d_out;

    cudaFuncSetAttribute(lstm_hmma, cudaFuncAttributeMaxDynamicSharedMemorySize,
                         SM_TOT);
    lstm_hmma<<<GCTAS, TTHR, SM_TOT>>>(X, E, Wi, bi, Wf, bf, Wo, bo, Wh, bh, out);
}

// round 9
// speedup vs baseline: 4.0547x; 1.0777x over previous
#include <cuda_runtime.h>
#include <cuda_bf16.h>
#include <cstdint>

#define NN 128
#define LL 512
#define HIDDEN 512
#define EMBED 256
#define GCTAS 128
#define TTHR 512

// CTA = (mslice: 32 rows) x (colgrp: 16 h-cols = 64 gate-cols)
// 16 warps = kq(warp>>2, K-split over tiles tile&3==kq) x nq(warp&3, 16 gate-cols)
// K = 768 logical j: [0,256) -> x (k=512+j), [256,768) -> h (k=j-256)
// 12 k64 tiles; tiles 0-3 pure x; A-ring of 3; reduction aliases the ring.

#define WSTR 1552
#define SM_WH 0
#define SM_WL 99328
#define SM_A  198656
#define ASTR  144
#define ASPL  4608
#define ABUF  9216
#define SM_TOT 226304

__device__ __nv_bfloat16 g_hh[2][NN * HIDDEN];
__device__ __nv_bfloat16 g_hl[2][NN * HIDDEN];
__device__ __nv_bfloat16 g_xh[LL][NN * EMBED];
__device__ __nv_bfloat16 g_xl[LL][NN * EMBED];
__device__ unsigned g_ecnt;
__device__ volatile unsigned g_egen;
__device__ unsigned g_cnt;
__device__ volatile unsigned g_gen;

__device__ __forceinline__ uint32_t smem_u32(const void* p) {
    uint32_t a;
    asm("{ .reg .u64 t; cvta.to.shared.u64 t, %1; cvt.u32.u64 %0, t; }" : "=r"(a) : "l"(p));
    return a;
}
__device__ __forceinline__ float sigf(float x) {
    return __fdividef(1.0f, 1.0f + __expf(-x));
}
__device__ __forceinline__ float tanhf_fast(float x) {
    return __fdividef(2.0f, 1.0f + __expf(-2.0f * x)) - 1.0f;
}

#define LDSM4(r0, r1, r2, r3, ad)                                                \
    asm volatile("ldmatrix.sync.aligned.m8n8.x4.shared.b16 {%0,%1,%2,%3}, [%4];" \
                 : "=r"(r0), "=r"(r1), "=r"(r2), "=r"(r3) : "r"(ad))

__device__ __forceinline__ void mma16816(float* d, uint32_t a0, uint32_t a1,
                                         uint32_t a2, uint32_t a3, uint32_t b0,
                                         uint32_t b1) {
    asm volatile(
        "mma.sync.aligned.m16n8k16.row.col.f32.bf16.bf16.f32 "
        "{%0,%1,%2,%3},{%4,%5,%6,%7},{%8,%9},{%0,%1,%2,%3};"
        : "+f"(d[0]), "+f"(d[1]), "+f"(d[2]), "+f"(d[3])
        : "r"(a0), "r"(a1), "r"(a2), "r"(a3), "r"(b0), "r"(b1));
}

__device__ __forceinline__ void entrybarrier() {
    __syncthreads();
    if (threadIdx.x == 0) {
        unsigned my = g_egen;
        __threadfence();
        unsigned old = atomicAdd(&g_ecnt, 1u);
        if (old == (GCTAS - 1)) {
            atomicExch(&g_ecnt, 0u);
            __threadfence();
            g_egen = my + 1u;
        } else {
            while (g_egen == my) { __nanosleep(64); }
        }
        __threadfence();
    }
    __syncthreads();
}

// stage one k64 tile (hi+lo, 32 rows x 128B each): 512 threads, 1 x 16B chunk each
__device__ __forceinline__ void stage(int tid, uint32_t su, int b, const char* ah,
                                      const char* al, int astr) {
    uint32_t dstb = su + SM_A + b * ABUF;
    int split = tid >> 8, row = (tid >> 3) & 31, ch = tid & 7;
    const char* src = (split ? al : ah) + row * astr + ch * 16;
    uint32_t dst = dstb + split * ASPL + row * ASTR + ch * 16;
    asm volatile("cp.async.cg.shared.global [%0], [%1], 16;" ::"r"(dst), "l"(src));
    asm volatile("cp.async.commit_group;" ::: "memory");
}

extern __shared__ char smem_raw[];

__global__ void __launch_bounds__(TTHR, 1)
lstm_hmma(const int* __restrict__ X, const float* __restrict__ E,
          const float* __restrict__ Wi, const float* __restrict__ bi,
          const float* __restrict__ Wf, const float* __restrict__ bf,
          const float* __restrict__ Wo, const float* __restrict__ bo,
          const float* __restrict__ Wh, const float* __restrict__ bh,
          float* __restrict__ out) {
    __shared__ int toks[NN];

    const int tid = threadIdx.x;
    const int warp = tid >> 5;
    const int lane = tid & 31;
    const int kq = warp >> 2;   // K-split group
    const int nq = warp & 3;    // N-group (16 gate-cols)
    const uint32_t su = smem_u32(smem_raw);
    char* dyn = smem_raw;
    float* red = (float*)(smem_raw + SM_A);   // reduction aliases A-ring

    const int mslice = blockIdx.x & 3;
    const int colgrp = blockIdx.x >> 2;
    const int mbase = mslice * 32;
    const int colbase = colgrp * 16;

    if (blockIdx.x == 0 && tid == 0) { g_cnt = 0u; g_gen = 0u; }

    // ---- weights resident in smem (hi + lo), rows n = hcol_local*4 + gate ----
    for (int n = 0; n < 64; n++) {
        int hc = colbase + (n >> 2), gate = n & 3;
        const float* Wg = (gate == 0) ? Wi : (gate == 1) ? Wf : (gate == 2) ? Wo : Wh;
        for (int j = tid; j < 768; j += TTHR) {
            int k = (j < 256) ? (512 + j) : (j - 256);
            float w = Wg[k * HIDDEN + hc];
            __nv_bfloat16 hi = __float2bfloat16(w);
            *(__nv_bfloat16*)(dyn + SM_WH + n * WSTR + j * 2) = hi;
            *(__nv_bfloat16*)(dyn + SM_WL + n * WSTR + j * 2) =
                __float2bfloat16(w - __bfloat162float(hi));
        }
    }

    // ---- embeddings (hi/lo), 4 timesteps per CTA, layout [t][m][e] ----
    for (int tt = 0; tt < 4; tt++) {
        int t = blockIdx.x * 4 + tt;
        __syncthreads();
        if (tid < NN) toks[tid] = X[tid * LL + t];
        __syncthreads();
        __nv_bfloat16* dh = g_xh[t];
        __nv_bfloat16* dl = g_xl[t];
        for (int i = tid; i < NN * EMBED; i += TTHR) {
            float v = E[(size_t)toks[i >> 8] * EMBED + (i & 255)];
            __nv_bfloat16 hi = __float2bfloat16(v);
            dh[i] = hi;
            dl[i] = __float2bfloat16(v - __bfloat162float(hi));
        }
    }
    if (tid < 256) {
        ((unsigned*)g_hh[0])[blockIdx.x * 256 + tid] = 0u;
        ((unsigned*)g_hl[0])[blockIdx.x * 256 + tid] = 0u;
    }

    // ---- ldmatrix base addresses ----
    const uint32_t a_off = (uint32_t)((lane & 15) * ASTR + (lane >> 4) * 16);
    const uint32_t bW_off =
        (uint32_t)((nq * 16 + (lane >> 4) * 8 + (lane & 7)) * WSTR +
                   ((lane >> 3) & 1) * 16);
    const uint32_t bWh = su + SM_WH + bW_off;
    const uint32_t bWl = su + SM_WL + bW_off;

    // ---- epilogue role: one cell per thread ----
    const int me = tid >> 4;      // 0..31
    const int hce = tid & 15;     // 0..15
    int bidx[4];
    float b4[4];
#pragma unroll
    for (int g = 0; g < 4; g++) {
        int n = hce * 4 + g;
        int nqr = n >> 4, nt = (n >> 3) & 1, nc = n & 7;
        int mt = me >> 4, mr = me & 15;
        int lane_r = (mr & 7) * 4 + (nc >> 1);
        int d = (mr >> 3) * 2 + (nc & 1);
        int f = mt * 8 + nt * 4 + d;
        bidx[g] = nqr * 512 + f * 32 + lane_r;
    }
    b4[0] = bi[colbase + hce];
    b4[1] = bf[colbase + hce];
    b4[2] = bo[colbase + hce];
    b4[3] = bh[colbase + hce];
    float cs = 0.0f;

    entrybarrier();

    // prologue: stage step-0 x tiles 0,1
    stage(tid, su, 0, (const char*)g_xh[0] + mbase * 512,
          (const char*)g_xl[0] + mbase * 512, 512);
    stage(tid, su, 1, (const char*)g_xh[0] + mbase * 512 + 128,
          (const char*)g_xl[0] + mbase * 512 + 128, 512);

    for (int t = 0; t < LL; t++) {
        float D0[2][2][4], D1a[2][2][4], D1b[2][2][4];
#pragma unroll
        for (int a = 0; a < 2; a++)
#pragma unroll
            for (int b = 0; b < 2; b++)
#pragma unroll
                for (int d = 0; d < 4; d++) {
                    D0[a][b][d] = 0.0f;
                    D1a[a][b][d] = 0.0f;
                    D1b[a][b][d] = 0.0f;
                }

#pragma unroll 1
        for (int tile = 0; tile < 12; tile++) {
            if (tile == 11)
                asm volatile("cp.async.wait_group 0;" ::: "memory");
            else
                asm volatile("cp.async.wait_group 1;" ::: "memory");
            __syncthreads();

            // stage tile+2 (within this step only; 10,11 deferred to epilogue)
            if (tile <= 9) {
                int nt = tile + 2;
                if (nt == 4) {   // first h tile: h_{t-1} must be published
                    while (g_gen < (unsigned)t) { __nanosleep(32); }
                }
                const char *ah, *al;
                int astr;
                if (nt < 4) {
                    ah = (const char*)g_xh[t] + mbase * 512 + nt * 128;
                    al = (const char*)g_xl[t] + mbase * 512 + nt * 128;
                    astr = 512;
                } else {
                    int hp = t & 1;
                    ah = (const char*)g_hh[hp] + mbase * 1024 + (nt - 4) * 128;
                    al = (const char*)g_hl[hp] + mbase * 1024 + (nt - 4) * 128;
                    astr = 1024;
                }
                stage(tid, su, nt % 3, ah, al, astr);
            }

            // ---- compute: only owner kq ----
            if ((tile & 3) == kq) {
                const uint32_t Ab = su + SM_A + (tile % 3) * ABUF + a_off;
#pragma unroll
                for (int kk = 0; kk < 4; kk++) {
                    const uint32_t kb = (uint32_t)(tile * 128 + kk * 32);
                    uint32_t bh0, bh1, bh2, bh3, bl0, bl1, bl2, bl3;
                    LDSM4(bh0, bh1, bh2, bh3, bWh + kb);
                    LDSM4(bl0, bl1, bl2, bl3, bWl + kb);
                    uint32_t ab = Ab + kk * 32;
                    uint32_t h00, h01, h02, h03, h10, h11, h12, h13;
                    uint32_t l00, l01, l02, l03, l10, l11, l12, l13;
                    LDSM4(h00, h01, h02, h03, ab);
                    LDSM4(h10, h11, h12, h13, ab + 16 * ASTR);
                    LDSM4(l00, l01, l02, l03, ab + ASPL);
                    LDSM4(l10, l11, l12, l13, ab + ASPL + 16 * ASTR);
                    mma16816(D0[0][0], h00, h01, h02, h03, bh0, bh1);
                    mma16816(D0[0][1], h00, h01, h02, h03, bh2, bh3);
                    mma16816(D0[1][0], h10, h11, h12, h13, bh0, bh1);
                    mma16816(D0[1][1], h10, h11, h12, h13, bh2, bh3);
                    mma16816(D1a[0][0], l00, l01, l02, l03, bh0, bh1);
                    mma16816(D1a[0][1], l00, l01, l02, l03, bh2, bh3);
                    mma16816(D1a[1][0], l10, l11, l12, l13, bh0, bh1);
                    mma16816(D1a[1][1], l10, l11, l12, l13, bh2, bh3);
                    mma16816(D1b[0][0], h00, h01, h02, h03, bl0, bl1);
                    mma16816(D1b[0][1], h00, h01, h02, h03, bl2, bl3);
                    mma16816(D1b[1][0], h10, h11, h12, h13, bl0, bl1);
                    mma16816(D1b[1][1], h10, h11, h12, h13, bl2, bl3);
                }
            }
        }

        // ---- merge chains ----
        float S[16];
#pragma unroll
        for (int a = 0; a < 2; a++)
#pragma unroll
            for (int b = 0; b < 2; b++)
#pragma unroll
                for (int d = 0; d < 4; d++)
                    S[a * 8 + b * 4 + d] =
                        D0[a][b][d] + D1a[a][b][d] + D1b[a][b][d];

        // ---- 2-phase cross-kq reduction through A-ring smem ----
        float a4[4];
        if (warp < 8) {   // kq 0,1
            int base = warp * 512 + lane;
#pragma unroll
            for (int f = 0; f < 16; f++) red[base + f * 32] = S[f];
        }
        __syncthreads();
#pragma unroll
        for (int g = 0; g < 4; g++) a4[g] = red[bidx[g]] + red[bidx[g] + 2048];
        __syncthreads();
        if (warp >= 8) {   // kq 2,3
            int base = (warp - 8) * 512 + lane;
#pragma unroll
            for (int f = 0; f < 16; f++) red[base + f * 32] = S[f];
        }
        __syncthreads();
#pragma unroll
        for (int g = 0; g < 4; g++) a4[g] += red[bidx[g]] + red[bidx[g] + 2048];
        __syncthreads();   // reads done before staging overwrites the ring

        // ---- gates + state update + publish ----
        const int pn = (t & 1) ^ 1;
        {
            float iv = sigf(a4[0] + b4[0]);
            float fv = sigf(a4[1] + b4[1]);
            float ov = sigf(a4[2] + b4[2]);
            float gv = tanhf_fast(a4[3] + b4[3]);
            cs = fv * cs + iv * gv;
            float hv = ov * tanhf_fast(cs);
            int mg = mbase + me, hcg = colbase + hce;
            __nv_bfloat16 hi = __float2bfloat16(hv);
            g_hh[pn][mg * HIDDEN + hcg] = hi;
            g_hl[pn][mg * HIDDEN + hcg] = __float2bfloat16(hv - __bfloat162float(hi));
            if (t == LL - 1) out[mg * HIDDEN + hcg] = hv;
        }

        // stage next step's x tiles 0,1 (independent of h)
        if (t + 1 < LL) {
            stage(tid, su, 0, (const char*)g_xh[t + 1] + mbase * 512,
                  (const char*)g_xl[t + 1] + mbase * 512, 512);
            stage(tid, su, 1, (const char*)g_xh[t + 1] + mbase * 512 + 128,
                  (const char*)g_xl[t + 1] + mbase * 512 + 128, 512);
        }

        __threadfence();
        __syncthreads();
        if (tid == 0) {
            unsigned old = atomicAdd(&g_cnt, 1u);
            if ((old & 127u) == 127u) {
                __threadfence();
                g_gen = (unsigned)(t + 1);
            }
        }
    }
}

extern "C" void kernel_launch(void* const* d_in, const int* in_sizes, int n_in,
                              void* d_out, int out_size) {
    const int* X = (const int*)d_in[0];
    const float* E = (const float*)d_in[1];
    const float* Wi = (const float*)d_in[2];
    const float* bi = (const float*)d_in[3];
    const float* Wf = (const float*)d_in[4];
    const float* bf = (const float*)d_in[5];
    const float* Wo = (const float*)d_in[6];
    const float* bo = (const float*)d_in[7];
    const float* Wh = (const float*)d_in[8];
    const float* bh = (const float*)d_in[9];
    float* out = (float*)d_out;

    cudaFuncSetAttribute(lstm_hmma, cudaFuncAttributeMaxDynamicSharedMemorySize,
                         SM_TOT);
    lstm_hmma<<<GCTAS, TTHR, SM_TOT>>>(X, E, Wi, bi, Wf, bf, Wo, bo, Wh, bh, out);
}

// round 11
// speedup vs baseline: 4.8180x; 1.1882x over previous
#include <cuda_runtime.h>
#include <cuda_bf16.h>
#include <cstdint>

#define NN 128
#define LL 512
#define HIDDEN 512
#define EMBED 256
#define GCTAS 128
#define TTHR 512

// CTA = (mslice: 32 rows) x (colgrp: 16 h-cols = 64 gate-cols)
// 16 warps = kq(warp>>2) x nq(warp&3); warp tile M32 x N16, owns tiles tile&3==kq
// K = 768 logical j: [0,256) -> x (k=512+j), [256,768) -> h (k=j-256)
// 12 k64 tiles = 6 pairs. Window w: wait pair w, COMPUTE pair w, then stage pair w+2.
// A ring: 4 tile-buffers of 8KB (XOR-swizzled 16B chunks). Reduction uses all 32KB
// of the ring at epilogue (ring fully drained by window5's wait_group 0).

#define WSTR 1552
#define SM_WH 0
#define SM_WL 99328
#define SM_A  198656
#define ABUF  8192
#define ASPL  4096
#define SM_TOT 231424        // 198656 + 4*8192

__device__ __nv_bfloat16 g_hh[2][NN * HIDDEN];
__device__ __nv_bfloat16 g_hl[2][NN * HIDDEN];
__device__ __nv_bfloat16 g_xh[LL][NN * EMBED];
__device__ __nv_bfloat16 g_xl[LL][NN * EMBED];
__device__ unsigned g_ecnt;
__device__ volatile unsigned g_egen;
__device__ unsigned g_cnt;
__device__ volatile unsigned g_gen;

__device__ __forceinline__ uint32_t smem_u32(const void* p) {
    uint32_t a;
    asm("{ .reg .u64 t; cvta.to.shared.u64 t, %1; cvt.u32.u64 %0, t; }" : "=r"(a) : "l"(p));
    return a;
}
__device__ __forceinline__ float sigf(float x) {
    return __fdividef(1.0f, 1.0f + __expf(-x));
}
__device__ __forceinline__ float tanhf_fast(float x) {
    return __fdividef(2.0f, 1.0f + __expf(-2.0f * x)) - 1.0f;
}

#define LDSM4(r0, r1, r2, r3, ad)                                                \
    asm volatile("ldmatrix.sync.aligned.m8n8.x4.shared.b16 {%0,%1,%2,%3}, [%4];" \
                 : "=r"(r0), "=r"(r1), "=r"(r2), "=r"(r3) : "r"(ad))

__device__ __forceinline__ void mma16816(float* d, uint32_t a0, uint32_t a1,
                                         uint32_t a2, uint32_t a3, uint32_t b0,
                                         uint32_t b1) {
    asm volatile(
        "mma.sync.aligned.m16n8k16.row.col.f32.bf16.bf16.f32 "
        "{%0,%1,%2,%3},{%4,%5,%6,%7},{%8,%9},{%0,%1,%2,%3};"
        : "+f"(d[0]), "+f"(d[1]), "+f"(d[2]), "+f"(d[3])
        : "r"(a0), "r"(a1), "r"(a2), "r"(a3), "r"(b0), "r"(b1));
}

__device__ __forceinline__ void entrybarrier() {
    __syncthreads();
    if (threadIdx.x == 0) {
        unsigned my = g_egen;
        __threadfence();
        unsigned old = atomicAdd(&g_ecnt, 1u);
        if (old == (GCTAS - 1)) {
            atomicExch(&g_ecnt, 0u);
            __threadfence();
            g_egen = my + 1u;
        } else {
            while (g_egen == my) { __nanosleep(64); }
        }
        __threadfence();
    }
    __syncthreads();
}

// stage a PAIR of k64 tiles (T, T+1) -> bufs T%4, (T+1)%4. One commit group.
__device__ __forceinline__ void stage_pair(int tid, uint32_t su, int T,
                                           const char* ah, const char* al,
                                           int astr, int koff0) {
    const int split = tid >> 8, row = (tid >> 3) & 31, ch = tid & 7;
    const uint32_t off =
        (uint32_t)(split * ASPL + row * 128 + ((ch ^ (row & 7)) << 4));
    const char* s0 = (split ? al : ah) + row * astr + koff0 + ch * 16;
    const char* s1 = s0 + 128;
    uint32_t d0 = su + SM_A + (uint32_t)((T & 3) * ABUF) + off;
    uint32_t d1 = su + SM_A + (uint32_t)(((T + 1) & 3) * ABUF) + off;
    asm volatile("cp.async.cg.shared.global [%0], [%1], 16;" ::"r"(d0), "l"(s0));
    asm volatile("cp.async.cg.shared.global [%0], [%1], 16;" ::"r"(d1), "l"(s1));
    asm volatile("cp.async.commit_group;" ::: "memory");
}

extern __shared__ char smem_raw[];

__global__ void __launch_bounds__(TTHR, 1)
lstm_hmma(const int* __restrict__ X, const float* __restrict__ E,
          const float* __restrict__ Wi, const float* __restrict__ bi,
          const float* __restrict__ Wf, const float* __restrict__ bf,
          const float* __restrict__ Wo, const float* __restrict__ bo,
          const float* __restrict__ Wh, const float* __restrict__ bh,
          float* __restrict__ out) {
    __shared__ int toks[NN];

    const int tid = threadIdx.x;
    const int warp = tid >> 5;
    const int lane = tid & 31;
    const int kq = warp >> 2;
    const int nq = warp & 3;
    const uint32_t su = smem_u32(smem_raw);
    char* dyn = smem_raw;
    float* red = (float*)(smem_raw + SM_A);   // epilogue-only: whole 32KB ring

    const int mslice = blockIdx.x & 3;
    const int colgrp = blockIdx.x >> 2;
    const int mbase = mslice * 32;
    const int colbase = colgrp * 16;

    if (blockIdx.x == 0 && tid == 0) { g_cnt = 0u; g_gen = 0u; }

    // ---- weights resident (hi + lo), rows n = hcol_local*4 + gate ----
    for (int n = 0; n < 64; n++) {
        int hc = colbase + (n >> 2), gate = n & 3;
        const float* Wg = (gate == 0) ? Wi : (gate == 1) ? Wf : (gate == 2) ? Wo : Wh;
        for (int j = tid; j < 768; j += TTHR) {
            int k = (j < 256) ? (512 + j) : (j - 256);
            float w = Wg[k * HIDDEN + hc];
            __nv_bfloat16 hi = __float2bfloat16(w);
            *(__nv_bfloat16*)(dyn + SM_WH + n * WSTR + j * 2) = hi;
            *(__nv_bfloat16*)(dyn + SM_WL + n * WSTR + j * 2) =
                __float2bfloat16(w - __bfloat162float(hi));
        }
    }

    // ---- embeddings (hi/lo), 4 timesteps per CTA, layout [t][m][e] ----
    for (int tt = 0; tt < 4; tt++) {
        int t = blockIdx.x * 4 + tt;
        __syncthreads();
        if (tid < NN) toks[tid] = X[tid * LL + t];
        __syncthreads();
        __nv_bfloat16* dh = g_xh[t];
        __nv_bfloat16* dl = g_xl[t];
        for (int i = tid; i < NN * EMBED; i += TTHR) {
            float v = E[(size_t)toks[i >> 8] * EMBED + (i & 255)];
            __nv_bfloat16 hi = __float2bfloat16(v);
            dh[i] = hi;
            dl[i] = __float2bfloat16(v - __bfloat162float(hi));
        }
    }
    if (tid < 256) {
        ((unsigned*)g_hh[0])[blockIdx.x * 256 + tid] = 0u;
        ((unsigned*)g_hl[0])[blockIdx.x * 256 + tid] = 0u;
    }

    // ---- A fragment addressing (swizzled; verified identical mapping to R9) ----
    const int row16 = lane & 15, c0 = lane >> 4, r7 = row16 & 7;
    const uint32_t arow = (uint32_t)(row16 * 128);
    // ---- B fragment addressing (padded resident W) ----
    const uint32_t bW_off =
        (uint32_t)((nq * 16 + (lane >> 4) * 8 + (lane & 7)) * WSTR +
                   ((lane >> 3) & 1) * 16);
    const uint32_t bWh = su + SM_WH + bW_off;
    const uint32_t bWl = su + SM_WL + bW_off;

    // ---- epilogue role: one cell per thread ----
    const int me = tid >> 4;
    const int hce = tid & 15;
    int bidx[4];
    float b4[4];
#pragma unroll
    for (int g = 0; g < 4; g++) {
        int n = hce * 4 + g;
        int nqr = n >> 4, nt = (n >> 3) & 1, nc = n & 7;
        int mt = me >> 4, mr = me & 15;
        int lane_r = (mr & 7) * 4 + (nc >> 1);
        int d = (mr >> 3) * 2 + (nc & 1);
        int f = mt * 8 + nt * 4 + d;
        bidx[g] = nqr * 512 + f * 32 + lane_r;   // + kq*2048 summed in gather
    }
    b4[0] = bi[colbase + hce];
    b4[1] = bf[colbase + hce];
    b4[2] = bo[colbase + hce];
    b4[3] = bh[colbase + hce];
    float cs = 0.0f;

    entrybarrier();

    // prologue: stage step-0 x pairs 0 (tiles 0,1) and 1 (tiles 2,3)
    stage_pair(tid, su, 0, (const char*)g_xh[0] + mbase * 512,
               (const char*)g_xl[0] + mbase * 512, 512, 0);
    stage_pair(tid, su, 2, (const char*)g_xh[0] + mbase * 512,
               (const char*)g_xl[0] + mbase * 512, 512, 256);

    for (int t = 0; t < LL; t++) {
        float D0[2][2][4], D1a[2][2][4], D1b[2][2][4];
#pragma unroll
        for (int a = 0; a < 2; a++)
#pragma unroll
            for (int b = 0; b < 2; b++)
#pragma unroll
                for (int d = 0; d < 4; d++) {
                    D0[a][b][d] = 0.0f;
                    D1a[a][b][d] = 0.0f;
                    D1b[a][b][d] = 0.0f;
                }

#pragma unroll 1
        for (int w = 0; w < 6; w++) {
            // outstanding groups at window start: {pair w, pair w+1} (w<5), {pair 5} (w=5)
            if (w == 5)
                asm volatile("cp.async.wait_group 0;" ::: "memory");
            else
                asm volatile("cp.async.wait_group 1;" ::: "memory");
            __syncthreads();

            // ---- compute own tile of pair w ----
            int T0 = 2 * w;
            int myT = -1;
            if ((T0 & 3) == kq) myT = T0;
            else if (((T0 + 1) & 3) == kq) myT = T0 + 1;
            if (myT >= 0) {
                const uint32_t Ab = su + SM_A + (uint32_t)((myT & 3) * ABUF) + arow;
#pragma unroll
                for (int kk = 0; kk < 4; kk++) {
                    const uint32_t kb = (uint32_t)(myT * 128 + kk * 32);
                    uint32_t bh0, bh1, bh2, bh3, bl0, bl1, bl2, bl3;
                    LDSM4(bh0, bh1, bh2, bh3, bWh + kb);
                    LDSM4(bl0, bl1, bl2, bl3, bWl + kb);
                    const uint32_t sw = (uint32_t)(((kk * 2 + c0) ^ r7) << 4);
                    uint32_t ab = Ab + sw;
                    uint32_t h00, h01, h02, h03, h10, h11, h12, h13;
                    uint32_t l00, l01, l02, l03, l10, l11, l12, l13;
                    LDSM4(h00, h01, h02, h03, ab);
                    LDSM4(h10, h11, h12, h13, ab + 2048);
                    LDSM4(l00, l01, l02, l03, ab + ASPL);
                    LDSM4(l10, l11, l12, l13, ab + ASPL + 2048);
                    mma16816(D0[0][0], h00, h01, h02, h03, bh0, bh1);
                    mma16816(D0[0][1], h00, h01, h02, h03, bh2, bh3);
                    mma16816(D0[1][0], h10, h11, h12, h13, bh0, bh1);
                    mma16816(D0[1][1], h10, h11, h12, h13, bh2, bh3);
                    mma16816(D1a[0][0], l00, l01, l02, l03, bh0, bh1);
                    mma16816(D1a[0][1], l00, l01, l02, l03, bh2, bh3);
                    mma16816(D1a[1][0], l10, l11, l12, l13, bh0, bh1);
                    mma16816(D1a[1][1], l10, l11, l12, l13, bh2, bh3);
                    mma16816(D1b[0][0], h00, h01, h02, h03, bl0, bl1);
                    mma16816(D1b[0][1], h00, h01, h02, h03, bl2, bl3);
                    mma16816(D1b[1][0], h10, h11, h12, h13, bl0, bl1);
                    mma16816(D1b[1][1], h10, h11, h12, h13, bl2, bl3);
                }
            }

            // ---- stage pair w+2 AFTER compute (and a barrier) — ring-safe ----
            if (w < 4) {
                __syncthreads();   // all warps done reading pair w's buffers
                int T = 2 * w + 4;   // h pairs (4,5),(6,7),(8,9),(10,11)
                if (w == 0) {
                    while (g_gen < (unsigned)t) { __nanosleep(32); }
                }
                int hp = t & 1;
                stage_pair(tid, su, T, (const char*)g_hh[hp] + mbase * 1024,
                           (const char*)g_hl[hp] + mbase * 1024, 1024,
                           (T - 4) * 128);
            }
        }

        // ---- merge chains ----
        float S[16];
#pragma unroll
        for (int a = 0; a < 2; a++)
#pragma unroll
            for (int b = 0; b < 2; b++)
#pragma unroll
                for (int d = 0; d < 4; d++)
                    S[a * 8 + b * 4 + d] =
                        D0[a][b][d] + D1a[a][b][d] + D1b[a][b][d];

        // ---- single-phase cross-kq reduction over the drained 32KB ring ----
        __syncthreads();   // all compute reads of ring done
        {
            int base = warp * 512 + lane;
#pragma unroll
            for (int f = 0; f < 16; f++) red[base + f * 32] = S[f];
        }
        __syncthreads();
        float a4[4];
#pragma unroll
        for (int g = 0; g < 4; g++)
            a4[g] = (red[bidx[g]] + red[bidx[g] + 2048]) +
                    (red[bidx[g] + 4096] + red[bidx[g] + 6144]);
        __syncthreads();   // reads done before staging overwrites the ring

        // ---- stage next step's x pairs 0,1 (pure x, no h dependency) ----
        if (t + 1 < LL) {
            stage_pair(tid, su, 0, (const char*)g_xh[t + 1] + mbase * 512,
                       (const char*)g_xl[t + 1] + mbase * 512, 512, 0);
            stage_pair(tid, su, 2, (const char*)g_xh[t + 1] + mbase * 512,
                       (const char*)g_xl[t + 1] + mbase * 512, 512, 256);
        }

        // ---- gates + state update + publish ----
        const int pn = (t & 1) ^ 1;
        {
            float iv = sigf(a4[0] + b4[0]);
            float fv = sigf(a4[1] + b4[1]);
            float ov = sigf(a4[2] + b4[2]);
            float gv = tanhf_fast(a4[3] + b4[3]);
            cs = fv * cs + iv * gv;
            float hv = ov * tanhf_fast(cs);
            int mg = mbase + me, hcg = colbase + hce;
            __nv_bfloat16 hi = __float2bfloat16(hv);
            g_hh[pn][mg * HIDDEN + hcg] = hi;
            g_hl[pn][mg * HIDDEN + hcg] = __float2bfloat16(hv - __bfloat162float(hi));
            if (t == LL - 1) out[mg * HIDDEN + hcg] = hv;
        }

        __threadfence();
        __syncthreads();
        if (tid == 0) {
            unsigned old = atomicAdd(&g_cnt, 1u);
            if ((old & 127u) == 127u) {
                __threadfence();
                g_gen = (unsigned)(t + 1);
            }
        }
    }
}

extern "C" void kernel_launch(void* const* d_in, const int* in_sizes, int n_in,
                              void* d_out, int out_size) {
    const int* X = (const int*)d_in[0];
    const float* E = (const float*)d_in[1];
    const float* Wi = (const float*)d_in[2];
    const float* bi = (const float*)d_in[3];
    const float* Wf = (const float*)d_in[4];
    const float* bf = (const float*)d_in[5];
    const float* Wo = (const float*)d_in[6];
    const float* bo = (const float*)d_in[7];
    const float* Wh = (const float*)d_in[8];
    const float* bh = (const float*)d_in[9];
    float* out = (float*)d_out;

    cudaFuncSetAttribute(lstm_hmma, cudaFuncAttributeMaxDynamicSharedMemorySize,
                         SM_TOT);
    lstm_hmma<<<GCTAS, TTHR, SM_TOT>>>(X, E, Wi, bi, Wf, bf, Wo, bo, Wh, bh, out);
}

// round 12
// speedup vs baseline: 5.0457x; 1.0473x over previous
#include <cuda_runtime.h>
#include <cuda_bf16.h>
#include <cstdint>

#define NN 128
#define LL 512
#define HIDDEN 512
#define EMBED 256
#define GCTAS 128
#define TTHR 512

// CTA = (mslice: 32 rows) x (colgrp: 16 h-cols = 64 gate-cols)
// 16 warps = kq(warp>>2) x nq(warp&3); warp tile M32 x N16.
// K = 768 logical j: [0,256) -> x (k=512+j), [256,768) -> h (k=j-256)
// 12 k64 tiles = 6 pairs. Window w: ALL warps active — warp (kq,nq) computes
// tile 2w+(kq>>1), kk half (kq&1). Stage pair w+2 after compute (ring-4 safe).
// h publication is per-mslice (fan-in 32), single tid0 release fence.

#define WSTR 1552
#define SM_WH 0
#define SM_WL 99328
#define SM_A  198656
#define ABUF  8192
#define ASPL  4096
#define SM_TOT 231424        // 198656 + 4*8192

__device__ __nv_bfloat16 g_hh[2][NN * HIDDEN];
__device__ __nv_bfloat16 g_hl[2][NN * HIDDEN];
__device__ __nv_bfloat16 g_xh[LL][NN * EMBED];
__device__ __nv_bfloat16 g_xl[LL][NN * EMBED];
__device__ unsigned g_ecnt;
__device__ volatile unsigned g_egen;
__device__ unsigned g_cntM[4 * 32];             // per-mslice arrival counters (padded)
__device__ volatile unsigned g_genM[4 * 32];    // per-mslice: == t+1 when h_t rows done

__device__ __forceinline__ uint32_t smem_u32(const void* p) {
    uint32_t a;
    asm("{ .reg .u64 t; cvta.to.shared.u64 t, %1; cvt.u32.u64 %0, t; }" : "=r"(a) : "l"(p));
    return a;
}
__device__ __forceinline__ float sigf(float x) {
    return __fdividef(1.0f, 1.0f + __expf(-x));
}
__device__ __forceinline__ float tanhf_fast(float x) {
    return __fdividef(2.0f, 1.0f + __expf(-2.0f * x)) - 1.0f;
}

#define LDSM4(r0, r1, r2, r3, ad)                                                \
    asm volatile("ldmatrix.sync.aligned.m8n8.x4.shared.b16 {%0,%1,%2,%3}, [%4];" \
                 : "=r"(r0), "=r"(r1), "=r"(r2), "=r"(r3) : "r"(ad))

__device__ __forceinline__ void mma16816(float* d, uint32_t a0, uint32_t a1,
                                         uint32_t a2, uint32_t a3, uint32_t b0,
                                         uint32_t b1) {
    asm volatile(
        "mma.sync.aligned.m16n8k16.row.col.f32.bf16.bf16.f32 "
        "{%0,%1,%2,%3},{%4,%5,%6,%7},{%8,%9},{%0,%1,%2,%3};"
        : "+f"(d[0]), "+f"(d[1]), "+f"(d[2]), "+f"(d[3])
        : "r"(a0), "r"(a1), "r"(a2), "r"(a3), "r"(b0), "r"(b1));
}

__device__ __forceinline__ void entrybarrier() {
    __syncthreads();
    if (threadIdx.x == 0) {
        unsigned my = g_egen;
        __threadfence();
        unsigned old = atomicAdd(&g_ecnt, 1u);
        if (old == (GCTAS - 1)) {
            atomicExch(&g_ecnt, 0u);
            __threadfence();
            g_egen = my + 1u;
        } else {
            while (g_egen == my) { __nanosleep(64); }
        }
        __threadfence();
    }
    __syncthreads();
}

// stage a PAIR of k64 tiles (T, T+1) -> bufs T%4, (T+1)%4. One commit group.
__device__ __forceinline__ void stage_pair(int tid, uint32_t su, int T,
                                           const char* ah, const char* al,
                                           int astr, int koff0) {
    const int split = tid >> 8, row = (tid >> 3) & 31, ch = tid & 7;
    const uint32_t off =
        (uint32_t)(split * ASPL + row * 128 + ((ch ^ (row & 7)) << 4));
    const char* s0 = (split ? al : ah) + row * astr + koff0 + ch * 16;
    const char* s1 = s0 + 128;
    uint32_t d0 = su + SM_A + (uint32_t)((T & 3) * ABUF) + off;
    uint32_t d1 = su + SM_A + (uint32_t)(((T + 1) & 3) * ABUF) + off;
    asm volatile("cp.async.cg.shared.global [%0], [%1], 16;" ::"r"(d0), "l"(s0));
    asm volatile("cp.async.cg.shared.global [%0], [%1], 16;" ::"r"(d1), "l"(s1));
    asm volatile("cp.async.commit_group;" ::: "memory");
}

extern __shared__ char smem_raw[];

__global__ void __launch_bounds__(TTHR, 1)
lstm_hmma(const int* __restrict__ X, const float* __restrict__ E,
          const float* __restrict__ Wi, const float* __restrict__ bi,
          const float* __restrict__ Wf, const float* __restrict__ bf,
          const float* __restrict__ Wo, const float* __restrict__ bo,
          const float* __restrict__ Wh, const float* __restrict__ bh,
          float* __restrict__ out) {
    __shared__ int toks[NN];

    const int tid = threadIdx.x;
    const int warp = tid >> 5;
    const int lane = tid & 31;
    const int kq = warp >> 2;
    const int nq = warp & 3;
    const uint32_t su = smem_u32(smem_raw);
    char* dyn = smem_raw;
    float* red = (float*)(smem_raw + SM_A);   // epilogue-only: whole 32KB ring

    const int mslice = blockIdx.x & 3;
    const int colgrp = blockIdx.x >> 2;
    const int mbase = mslice * 32;
    const int colbase = colgrp * 16;

    if (blockIdx.x == 0 && tid < 4) {
        g_cntM[tid * 32] = 0u;
        g_genM[tid * 32] = 0u;
    }

    // ---- weights resident (hi + lo), rows n = hcol_local*4 + gate ----
    for (int n = 0; n < 64; n++) {
        int hc = colbase + (n >> 2), gate = n & 3;
        const float* Wg = (gate == 0) ? Wi : (gate == 1) ? Wf : (gate == 2) ? Wo : Wh;
        for (int j = tid; j < 768; j += TTHR) {
            int k = (j < 256) ? (512 + j) : (j - 256);
            float w = Wg[k * HIDDEN + hc];
            __nv_bfloat16 hi = __float2bfloat16(w);
            *(__nv_bfloat16*)(dyn + SM_WH + n * WSTR + j * 2) = hi;
            *(__nv_bfloat16*)(dyn + SM_WL + n * WSTR + j * 2) =
                __float2bfloat16(w - __bfloat162float(hi));
        }
    }

    // ---- embeddings (hi/lo), 4 timesteps per CTA, layout [t][m][e] ----
    for (int tt = 0; tt < 4; tt++) {
        int t = blockIdx.x * 4 + tt;
        __syncthreads();
        if (tid < NN) toks[tid] = X[tid * LL + t];
        __syncthreads();
        __nv_bfloat16* dh = g_xh[t];
        __nv_bfloat16* dl = g_xl[t];
        for (int i = tid; i < NN * EMBED; i += TTHR) {
            float v = E[(size_t)toks[i >> 8] * EMBED + (i & 255)];
            __nv_bfloat16 hi = __float2bfloat16(v);
            dh[i] = hi;
            dl[i] = __float2bfloat16(v - __bfloat162float(hi));
        }
    }
    if (tid < 256) {
        ((unsigned*)g_hh[0])[blockIdx.x * 256 + tid] = 0u;
        ((unsigned*)g_hl[0])[blockIdx.x * 256 + tid] = 0u;
    }

    // ---- A fragment addressing (swizzled; R9/R11-verified mapping) ----
    const int row16 = lane & 15, c0 = lane >> 4, r7 = row16 & 7;
    const uint32_t arow = (uint32_t)(row16 * 128);
    // ---- B fragment addressing (padded resident W) ----
    const uint32_t bW_off =
        (uint32_t)((nq * 16 + (lane >> 4) * 8 + (lane & 7)) * WSTR +
                   ((lane >> 3) & 1) * 16);
    const uint32_t bWh = su + SM_WH + bW_off;
    const uint32_t bWl = su + SM_WL + bW_off;

    // ---- this warp's fixed tile/kk assignment within each window ----
    const int tsel = kq >> 1;        // which tile of the pair
    const int kk0 = (kq & 1) * 2;    // which kk half

    // ---- epilogue role: one cell per thread ----
    const int me = tid >> 4;
    const int hce = tid & 15;
    int bidx[4];
    float b4[4];
#pragma unroll
    for (int g = 0; g < 4; g++) {
        int n = hce * 4 + g;
        int nqr = n >> 4, nt = (n >> 3) & 1, nc = n & 7;
        int mt = me >> 4, mr = me & 15;
        int lane_r = (mr & 7) * 4 + (nc >> 1);
        int d = (mr >> 3) * 2 + (nc & 1);
        int f = mt * 8 + nt * 4 + d;
        bidx[g] = nqr * 512 + f * 32 + lane_r;   // + kq*2048 summed in gather
    }
    b4[0] = bi[colbase + hce];
    b4[1] = bf[colbase + hce];
    b4[2] = bo[colbase + hce];
    b4[3] = bh[colbase + hce];
    float cs = 0.0f;

    entrybarrier();

    // prologue: stage step-0 x pairs 0 (tiles 0,1) and 1 (tiles 2,3)
    stage_pair(tid, su, 0, (const char*)g_xh[0] + mbase * 512,
               (const char*)g_xl[0] + mbase * 512, 512, 0);
    stage_pair(tid, su, 2, (const char*)g_xh[0] + mbase * 512,
               (const char*)g_xl[0] + mbase * 512, 512, 256);

    for (int t = 0; t < LL; t++) {
        float D0[2][2][4], D1a[2][2][4], D1b[2][2][4];
#pragma unroll
        for (int a = 0; a < 2; a++)
#pragma unroll
            for (int b = 0; b < 2; b++)
#pragma unroll
                for (int d = 0; d < 4; d++) {
                    D0[a][b][d] = 0.0f;
                    D1a[a][b][d] = 0.0f;
                    D1b[a][b][d] = 0.0f;
                }

#pragma unroll 1
        for (int w = 0; w < 6; w++) {
            if (w == 5)
                asm volatile("cp.async.wait_group 0;" ::: "memory");
            else
                asm volatile("cp.async.wait_group 1;" ::: "memory");
            __syncthreads();

            // ---- compute: every warp works its (tile, kk-half) of pair w ----
            {
                const int myT = 2 * w + tsel;
                const uint32_t Ab = su + SM_A + (uint32_t)((myT & 3) * ABUF) + arow;
#pragma unroll
                for (int kx = 0; kx < 2; kx++) {
                    const int kk = kk0 + kx;
                    const uint32_t kb = (uint32_t)(myT * 128 + kk * 32);
                    uint32_t bh0, bh1, bh2, bh3, bl0, bl1, bl2, bl3;
                    LDSM4(bh0, bh1, bh2, bh3, bWh + kb);
                    LDSM4(bl0, bl1, bl2, bl3, bWl + kb);
                    const uint32_t sw = (uint32_t)(((kk * 2 + c0) ^ r7) << 4);
                    uint32_t ab = Ab + sw;
                    uint32_t h00, h01, h02, h03, h10, h11, h12, h13;
                    uint32_t l00, l01, l02, l03, l10, l11, l12, l13;
                    LDSM4(h00, h01, h02, h03, ab);
                    LDSM4(h10, h11, h12, h13, ab + 2048);
                    LDSM4(l00, l01, l02, l03, ab + ASPL);
                    LDSM4(l10, l11, l12, l13, ab + ASPL + 2048);
                    mma16816(D0[0][0], h00, h01, h02, h03, bh0, bh1);
                    mma16816(D0[0][1], h00, h01, h02, h03, bh2, bh3);
                    mma16816(D0[1][0], h10, h11, h12, h13, bh0, bh1);
                    mma16816(D0[1][1], h10, h11, h12, h13, bh2, bh3);
                    mma16816(D1a[0][0], l00, l01, l02, l03, bh0, bh1);
                    mma16816(D1a[0][1], l00, l01, l02, l03, bh2, bh3);
                    mma16816(D1a[1][0], l10, l11, l12, l13, bh0, bh1);
                    mma16816(D1a[1][1], l10, l11, l12, l13, bh2, bh3);
                    mma16816(D1b[0][0], h00, h01, h02, h03, bl0, bl1);
                    mma16816(D1b[0][1], h00, h01, h02, h03, bl2, bl3);
                    mma16816(D1b[1][0], h10, h11, h12, h13, bl0, bl1);
                    mma16816(D1b[1][1], h10, h11, h12, h13, bl2, bl3);
                }
            }

            // ---- stage pair w+2 AFTER compute (ring-4 safe) ----
            if (w < 4) {
                __syncthreads();   // all warps done reading pair w's buffers
                int T = 2 * w + 4;   // h pairs (4,5),(6,7),(8,9),(10,11)
                if (w == 0) {
                    while (g_genM[mslice * 32] < (unsigned)t) { __nanosleep(32); }
                }
                int hp = t & 1;
                stage_pair(tid, su, T, (const char*)g_hh[hp] + mbase * 1024,
                           (const char*)g_hl[hp] + mbase * 1024, 1024,
                           (T - 4) * 128);
            }
        }

        // ---- merge chains ----
        float S[16];
#pragma unroll
        for (int a = 0; a < 2; a++)
#pragma unroll
            for (int b = 0; b < 2; b++)
#pragma unroll
                for (int d = 0; d < 4; d++)
                    S[a * 8 + b * 4 + d] =
                        D0[a][b][d] + D1a[a][b][d] + D1b[a][b][d];

        // ---- single-phase cross-kq reduction over the drained 32KB ring ----
        __syncthreads();
        {
            int base = warp * 512 + lane;
#pragma unroll
            for (int f = 0; f < 16; f++) red[base + f * 32] = S[f];
        }
        __syncthreads();
        float a4[4];
#pragma unroll
        for (int g = 0; g < 4; g++)
            a4[g] = (red[bidx[g]] + red[bidx[g] + 2048]) +
                    (red[bidx[g] + 4096] + red[bidx[g] + 6144]);
        __syncthreads();   // reads done before staging overwrites the ring

        // ---- stage next step's x pairs 0,1 (pure x, no h dependency) ----
        if (t + 1 < LL) {
            stage_pair(tid, su, 0, (const char*)g_xh[t + 1] + mbase * 512,
                       (const char*)g_xl[t + 1] + mbase * 512, 512, 0);
            stage_pair(tid, su, 2, (const char*)g_xh[t + 1] + mbase * 512,
                       (const char*)g_xl[t + 1] + mbase * 512, 512, 256);
        }

        // ---- gates + state update + publish ----
        const int pn = (t & 1) ^ 1;
        {
            float iv = sigf(a4[0] + b4[0]);
            float fv = sigf(a4[1] + b4[1]);
            float ov = sigf(a4[2] + b4[2]);
            float gv = tanhf_fast(a4[3] + b4[3]);
            cs = fv * cs + iv * gv;
            float hv = ov * tanhf_fast(cs);
            int mg = mbase + me, hcg = colbase + hce;
            __nv_bfloat16 hi = __float2bfloat16(hv);
            g_hh[pn][mg * HIDDEN + hcg] = hi;
            g_hl[pn][mg * HIDDEN + hcg] = __float2bfloat16(hv - __bfloat162float(hi));
            if (t == LL - 1) out[mg * HIDDEN + hcg] = hv;
        }

        // ---- per-mslice release publish: 1 fence, fan-in 32 ----
        __syncthreads();
        if (tid == 0) {
            __threadfence();
            unsigned old = atomicAdd(&g_cntM[mslice * 32], 1u);
            if ((old & 31u) == 31u) {
                __threadfence();
                g_genM[mslice * 32] = (unsigned)(t + 1);
            }
        }
    }
}

extern "C" void kernel_launch(void* const* d_in, const int* in_sizes, int n_in,
                              void* d_out, int out_size) {
    const int* X = (const int*)d_in[0];
    const float* E = (const float*)d_in[1];
    const float* Wi = (const float*)d_in[2];
    const float* bi = (const float*)d_in[3];
    const float* Wf = (const float*)d_in[4];
    const float* bf = (const float*)d_in[5];
    const float* Wo = (const float*)d_in[6];
    const float* bo = (const float*)d_in[7];
    const float* Wh = (const float*)d_in[8];
    const float* bh = (const float*)d_in[9];
    float* out = (float*)d_out;

    cudaFuncSetAttribute(lstm_hmma, cudaFuncAttributeMaxDynamicSharedMemorySize,
                         SM_TOT);
    lstm_hmma<<<GCTAS, TTHR, SM_TOT>>>(X, E, Wi, bi, Wf, bf, Wo, bo, Wh, bh, out);
}